// round 2
// baseline (speedup 1.0000x reference)
#include <cuda_runtime.h>
#include <cuda_bf16.h>
#include <cstddef>
#include <cstdint>

// ---------------------------------------------------------------------------
// dygraphSAGE: 2x GraphSAGE(mean) layers + temporal fusion + leakyrelu + l2norm
// Shapes (fixed by dataset): N=100000, E=1600000, D=128, G=3, num=50000
// ---------------------------------------------------------------------------

#define D128 128
#define MAXN 131072
#define MAXE 2097152

// scratch (device globals -- allocation-free per harness rules)
__device__ float g_agg  [(size_t)MAXN * D128];
__device__ float g_feat1[(size_t)MAXN * D128];
__device__ float g_feat2[(size_t)MAXN * D128];
__device__ float g_invdeg[MAXN];
__device__ int   g_cnt[MAXN];
__device__ float g_Wcat[384 * D128];
__device__ int   g_idx[2 * MAXE];     // normalized int32 [src | dst]
__device__ int   g_is64;

// ---------------------------------------------------------------------------
// index dtype sniff + normalize (edge_index may be int32 or int64 on device)
// If int64 (LE, values < 2^31): odd int32 slots of first E entries are all 0.
// ---------------------------------------------------------------------------
__global__ void detect_kernel(const int* __restrict__ ei, int E) {
    __shared__ int any;
    if (threadIdx.x == 0) any = 0;
    __syncthreads();
    int cnt = E < 4096 ? E : 4096;
    for (int i = threadIdx.x; i < cnt; i += blockDim.x)
        if (ei[2 * i + 1] != 0) any = 1;
    __syncthreads();
    if (threadIdx.x == 0) g_is64 = any ? 0 : 1;
}

__global__ void convert_kernel(const void* __restrict__ ei, int* __restrict__ out,
                               int total) {
    int i = blockIdx.x * blockDim.x + threadIdx.x;
    if (i >= total) return;
    if (g_is64) out[i] = (int)((const long long*)ei)[i];
    else        out[i] = ((const int*)ei)[i];
}

// ---------------------------------------------------------------------------
// degree count + inverse degree
// ---------------------------------------------------------------------------
__global__ void deg_kernel(const int* __restrict__ dst, int* __restrict__ cnt, int E) {
    int e = blockIdx.x * blockDim.x + threadIdx.x;
    if (e < E) atomicAdd(&cnt[dst[e]], 1);
}

__global__ void invdeg_kernel(const int* __restrict__ cnt, float* __restrict__ invd, int n) {
    int i = blockIdx.x * blockDim.x + threadIdx.x;
    if (i < n) {
        int c = cnt[i];
        invd[i] = 1.0f / (float)(c > 1 ? c : 1);
    }
}

// ---------------------------------------------------------------------------
// edge aggregation: one warp per edge, vectorized float4 RED into agg[dst]
// ---------------------------------------------------------------------------
__global__ void aggregate_kernel(const float* __restrict__ feat,
                                 const int* __restrict__ src,
                                 const int* __restrict__ dst,
                                 float* __restrict__ agg, int E) {
    int w    = (int)((blockIdx.x * (size_t)blockDim.x + threadIdx.x) >> 5);
    int lane = threadIdx.x & 31;
    if (w >= E) return;
    int s = src[w];
    int d = dst[w];
    const float4 v = *(const float4*)&feat[(size_t)s * D128 + lane * 4];
    float* p = &agg[(size_t)d * D128 + lane * 4];
    asm volatile("red.global.add.v4.f32 [%0], {%1,%2,%3,%4};"
                 :: "l"(p), "f"(v.x), "f"(v.y), "f"(v.z), "f"(v.w)
                 : "memory");
}

// ---------------------------------------------------------------------------
// SAGE layer GEMM: OUT = relu([H | AGG*invdeg] @ W), W is [256,128] row-major
// 128x128 output tile per block, 256 threads, 8x8 accum per thread.
// Optionally streams rows >= numTail into `tail` (final-output tail copy).
// ---------------------------------------------------------------------------
__global__ __launch_bounds__(256)
void gemm_sage(const float* __restrict__ H, const float* __restrict__ AGG,
               const float* __restrict__ invd, const float* __restrict__ W,
               float* __restrict__ OUT, float* __restrict__ tail,
               int n, int numTail) {
    __shared__ float As[16][132];   // [k][m], padded
    __shared__ float Bs[16][128];   // [k][n]

    const int row0 = blockIdx.x * 128;
    const int tid  = threadIdx.x;
    const int ty   = tid >> 4;      // 0..15 -> rows ty*8..+7
    const int tx   = tid & 15;      // 0..15 -> cols tx*8..+7

    float acc[8][8];
#pragma unroll
    for (int i = 0; i < 8; i++)
#pragma unroll
        for (int j = 0; j < 8; j++) acc[i][j] = 0.0f;

    for (int kb = 0; kb < 256; kb += 16) {
        // load A chunk: 128 rows x 16 k  (512 float4, 2 per thread)
#pragma unroll
        for (int l = 0; l < 2; l++) {
            int idx = tid + l * 256;
            int r   = idx >> 2;
            int kq  = idx & 3;
            int row = row0 + r;
            float4 v = make_float4(0.f, 0.f, 0.f, 0.f);
            if (row < n) {
                int k = kb + kq * 4;
                if (k < 128) {
                    v = *(const float4*)&H[(size_t)row * D128 + k];
                } else {
                    v = *(const float4*)&AGG[(size_t)row * D128 + (k - 128)];
                    float s = invd[row];
                    v.x *= s; v.y *= s; v.z *= s; v.w *= s;
                }
            }
            As[kq * 4 + 0][r] = v.x;
            As[kq * 4 + 1][r] = v.y;
            As[kq * 4 + 2][r] = v.z;
            As[kq * 4 + 3][r] = v.w;
        }
        // load B chunk: 16 x 128 (512 float4, 2 per thread)
#pragma unroll
        for (int l = 0; l < 2; l++) {
            int idx = tid + l * 256;
            int k   = idx >> 5;
            int c   = (idx & 31) * 4;
            *(float4*)&Bs[k][c] = *(const float4*)&W[(size_t)(kb + k) * D128 + c];
        }
        __syncthreads();
#pragma unroll
        for (int k = 0; k < 16; k++) {
            float a[8], b[8];
            *(float4*)&a[0] = *(const float4*)&As[k][ty * 8];
            *(float4*)&a[4] = *(const float4*)&As[k][ty * 8 + 4];
            *(float4*)&b[0] = *(const float4*)&Bs[k][tx * 8];
            *(float4*)&b[4] = *(const float4*)&Bs[k][tx * 8 + 4];
#pragma unroll
            for (int i = 0; i < 8; i++)
#pragma unroll
                for (int j = 0; j < 8; j++)
                    acc[i][j] = fmaf(a[i], b[j], acc[i][j]);
        }
        __syncthreads();
    }

    // epilogue: relu + store (+ tail copy)
#pragma unroll
    for (int i = 0; i < 8; i++) {
        int row = row0 + ty * 8 + i;
        if (row >= n) continue;
#pragma unroll
        for (int j = 0; j < 8; j += 4) {
            float4 v;
            v.x = fmaxf(acc[i][j + 0], 0.f);
            v.y = fmaxf(acc[i][j + 1], 0.f);
            v.z = fmaxf(acc[i][j + 2], 0.f);
            v.w = fmaxf(acc[i][j + 3], 0.f);
            *(float4*)&OUT[(size_t)row * D128 + tx * 8 + j] = v;
            if (tail != nullptr && row >= numTail)
                *(float4*)&tail[(size_t)row * D128 + tx * 8 + j] = v;
        }
    }
}

// ---------------------------------------------------------------------------
// Combine the temporal weights into one [384,128] matrix:
//   Wcat[0:128]   = W_T_top + (W0  @ W_T_bot)/3
//   Wcat[128:256] = (Wp[0] @ W_T_bot)/3
//   Wcat[256:384] = (Wp[1] @ W_T_bot)/3
// grid (128, 3), block 128
// ---------------------------------------------------------------------------
__global__ void wcombine_kernel(const float* __restrict__ W0,
                                const float* __restrict__ Wp,
                                const float* __restrict__ WT,
                                float* __restrict__ Wcat) {
    int row = blockIdx.x;
    int m   = blockIdx.y;
    int col = threadIdx.x;
    __shared__ float L[128];
    const float* Lsrc = (m == 0) ? W0 : (Wp + (size_t)(m - 1) * 128 * 128);
    L[col] = Lsrc[row * 128 + col];
    __syncthreads();
    float s = 0.f;
#pragma unroll 8
    for (int k = 0; k < 128; k++)
        s = fmaf(L[k], WT[(size_t)(128 + k) * 128 + col], s);
    s *= (1.0f / 3.0f);
    if (m == 0) s += WT[(size_t)row * 128 + col];
    Wcat[(size_t)(m * 128 + row) * 128 + col] = s;
}

// ---------------------------------------------------------------------------
// Final fused kernel over rows < num:
//   f = leakyrelu([feat2 | past0 | past1] @ Wcat, 0.2); out = f / max(||f||,1e-12)
// Same tiling as gemm_sage but K=384 from three sources; row-norm via shfl
// reduction across the 16 tx lanes owning a row.
// ---------------------------------------------------------------------------
__global__ __launch_bounds__(256)
void gemm_final(const float* __restrict__ F2, const float* __restrict__ P0,
                const float* __restrict__ P1, const float* __restrict__ Wc,
                float* __restrict__ OUT, int num) {
    __shared__ float As[16][132];
    __shared__ float Bs[16][128];

    const int row0 = blockIdx.x * 128;
    const int tid  = threadIdx.x;
    const int ty   = tid >> 4;
    const int tx   = tid & 15;

    float acc[8][8];
#pragma unroll
    for (int i = 0; i < 8; i++)
#pragma unroll
        for (int j = 0; j < 8; j++) acc[i][j] = 0.0f;

    for (int kb = 0; kb < 384; kb += 16) {
#pragma unroll
        for (int l = 0; l < 2; l++) {
            int idx = tid + l * 256;
            int r   = idx >> 2;
            int kq  = idx & 3;
            int row = row0 + r;
            float4 v = make_float4(0.f, 0.f, 0.f, 0.f);
            if (row < num) {
                int k = kb + kq * 4;
                if (k < 128)       v = *(const float4*)&F2[(size_t)row * D128 + k];
                else if (k < 256)  v = *(const float4*)&P0[(size_t)row * D128 + (k - 128)];
                else               v = *(const float4*)&P1[(size_t)row * D128 + (k - 256)];
            }
            As[kq * 4 + 0][r] = v.x;
            As[kq * 4 + 1][r] = v.y;
            As[kq * 4 + 2][r] = v.z;
            As[kq * 4 + 3][r] = v.w;
        }
#pragma unroll
        for (int l = 0; l < 2; l++) {
            int idx = tid + l * 256;
            int k   = idx >> 5;
            int c   = (idx & 31) * 4;
            *(float4*)&Bs[k][c] = *(const float4*)&Wc[(size_t)(kb + k) * D128 + c];
        }
        __syncthreads();
#pragma unroll
        for (int k = 0; k < 16; k++) {
            float a[8], b[8];
            *(float4*)&a[0] = *(const float4*)&As[k][ty * 8];
            *(float4*)&a[4] = *(const float4*)&As[k][ty * 8 + 4];
            *(float4*)&b[0] = *(const float4*)&Bs[k][tx * 8];
            *(float4*)&b[4] = *(const float4*)&Bs[k][tx * 8 + 4];
#pragma unroll
            for (int i = 0; i < 8; i++)
#pragma unroll
                for (int j = 0; j < 8; j++)
                    acc[i][j] = fmaf(a[i], b[j], acc[i][j]);
        }
        __syncthreads();
    }

    // leaky relu + per-row sum of squares (partial over this thread's 8 cols)
    float p[8];
#pragma unroll
    for (int i = 0; i < 8; i++) {
        float s = 0.f;
#pragma unroll
        for (int j = 0; j < 8; j++) {
            float v = acc[i][j];
            v = (v > 0.f) ? v : 0.2f * v;
            acc[i][j] = v;
            s = fmaf(v, v, s);
        }
        p[i] = s;
    }
    // reduce across the 16 tx lanes owning each row (xor masks stay in-half)
#pragma unroll
    for (int m = 1; m < 16; m <<= 1) {
#pragma unroll
        for (int i = 0; i < 8; i++)
            p[i] += __shfl_xor_sync(0xffffffffu, p[i], m);
    }
#pragma unroll
    for (int i = 0; i < 8; i++) {
        int row = row0 + ty * 8 + i;
        if (row >= num) continue;
        float inv = 1.0f / fmaxf(sqrtf(p[i]), 1e-12f);
#pragma unroll
        for (int j = 0; j < 8; j += 4) {
            float4 v;
            v.x = acc[i][j + 0] * inv;
            v.y = acc[i][j + 1] * inv;
            v.z = acc[i][j + 2] * inv;
            v.w = acc[i][j + 3] * inv;
            *(float4*)&OUT[(size_t)row * D128 + tx * 8 + j] = v;
        }
    }
}

// ---------------------------------------------------------------------------
// launch
// ---------------------------------------------------------------------------
extern "C" void kernel_launch(void* const* d_in, const int* in_sizes, int n_in,
                              void* d_out, int out_size) {
    const float* x    = (const float*)d_in[0];        // [N,128]
    const float* past = (const float*)d_in[1];        // [2,num,128]
    const float* W1   = (const float*)d_in[2];        // [256,128]
    const float* W2   = (const float*)d_in[3];        // [256,128]
    const float* W0   = (const float*)d_in[4];        // [128,128]
    const float* Wp   = (const float*)d_in[5];        // [2,128,128]
    const float* WT   = (const float*)d_in[6];        // [256,128]
    const void*  ei   = d_in[7];                      // [2,E] int32 or int64
    float*       out  = (float*)d_out;                // [N,128]

    const int n   = in_sizes[0] / D128;
    const int num = in_sizes[1] / (2 * D128);
    const int E   = in_sizes[7] / 2;

    const float* p0 = past;
    const float* p1 = past + (size_t)num * D128;

    float *agg, *feat1, *feat2, *invd, *Wcat;
    int   *cnt, *idx;
    cudaGetSymbolAddress((void**)&agg,   g_agg);
    cudaGetSymbolAddress((void**)&feat1, g_feat1);
    cudaGetSymbolAddress((void**)&feat2, g_feat2);
    cudaGetSymbolAddress((void**)&invd,  g_invdeg);
    cudaGetSymbolAddress((void**)&cnt,   g_cnt);
    cudaGetSymbolAddress((void**)&Wcat,  g_Wcat);
    cudaGetSymbolAddress((void**)&idx,   g_idx);

    const int* src = idx;
    const int* dst = idx + E;

    const size_t featBytes = (size_t)n * D128 * sizeof(float);

    // normalize edge indices to int32 (handles int32 or int64 source)
    detect_kernel<<<1, 256>>>((const int*)ei, E);
    convert_kernel<<<(2 * E + 255) / 256, 256>>>(ei, idx, 2 * E);

    // degrees
    cudaMemsetAsync(cnt, 0, (size_t)n * sizeof(int));
    cudaMemsetAsync(agg, 0, featBytes);
    deg_kernel<<<(E + 255) / 256, 256>>>(dst, cnt, E);
    invdeg_kernel<<<(n + 255) / 256, 256>>>(cnt, invd, n);

    const int aggBlocks  = (E + 7) / 8;          // 8 warps (edges) per block
    const int gemmBlocks = (n + 127) / 128;

    // layer 1
    aggregate_kernel<<<aggBlocks, 256>>>(x, src, dst, agg, E);
    gemm_sage<<<gemmBlocks, 256>>>(x, agg, invd, W1, feat1, nullptr, n, n);

    // layer 2 (tail rows >= num stream straight into d_out)
    cudaMemsetAsync(agg, 0, featBytes);
    aggregate_kernel<<<aggBlocks, 256>>>(feat1, src, dst, agg, E);
    gemm_sage<<<gemmBlocks, 256>>>(feat1, agg, invd, W2, feat2, out, n, num);

    // fold temporal weights, then fused final GEMM + leakyrelu + l2 normalize
    {
        dim3 g(128, 3);
        wcombine_kernel<<<g, 128>>>(W0, Wp, WT, Wcat);
    }
    gemm_final<<<(num + 127) / 128, 256>>>(feat2, p0, p1, Wcat, out, num);
}

// round 4
// speedup vs baseline: 1.2398x; 1.2398x over previous
#include <cuda_runtime.h>
#include <cuda_bf16.h>
#include <cstddef>
#include <cstdint>

// ---------------------------------------------------------------------------
// dygraphSAGE on GB300 (base sm_103 target): GEMMs via mma.sync bf16 hi/lo
// ---------------------------------------------------------------------------

#define D128 128
#define MAXN 131072
#define MAXE 2097152

// scratch (device globals -- allocation-free per harness rules)
__device__ float g_agg  [(size_t)MAXN * D128];
__device__ float g_feat1[(size_t)MAXN * D128];
__device__ float g_feat2[(size_t)MAXN * D128];
__device__ float g_invdeg[MAXN];
__device__ int   g_cnt[MAXN];
__device__ float g_Wcat[384 * D128];
__device__ int   g_idx[2 * MAXE];
__device__ int   g_is64;
// pre-baked transposed weights Bt[n][k] bf16, hi image then lo image
__device__ __align__(16) uint16_t g_B1[2 * 128 * 256];
__device__ __align__(16) uint16_t g_B2[2 * 128 * 256];
__device__ __align__(16) uint16_t g_Bf[2 * 128 * 384];

// ---------------------------------------------------------------------------
// helpers
// ---------------------------------------------------------------------------
__device__ __forceinline__ void split2(float x0, float x1, uint32_t& hi, uint32_t& lo) {
    // hi = {bf16(x1) | bf16(x0)} (x0 in low half), lo = residual pair
    asm("cvt.rn.bf16x2.f32 %0, %1, %2;" : "=r"(hi) : "f"(x1), "f"(x0));
    float h0 = __uint_as_float(hi << 16);
    float h1 = __uint_as_float(hi & 0xffff0000u);
    asm("cvt.rn.bf16x2.f32 %0, %1, %2;" : "=r"(lo) : "f"(x1 - h1), "f"(x0 - h0));
}

__device__ __forceinline__ void mma16816(float* c, const uint32_t* a, const uint32_t* b) {
    asm volatile("mma.sync.aligned.m16n8k16.row.col.f32.bf16.bf16.f32 "
                 "{%0,%1,%2,%3}, {%4,%5,%6,%7}, {%8,%9}, {%0,%1,%2,%3};"
                 : "+f"(c[0]), "+f"(c[1]), "+f"(c[2]), "+f"(c[3])
                 : "r"(a[0]), "r"(a[1]), "r"(a[2]), "r"(a[3]),
                   "r"(b[0]), "r"(b[1]));
}

// ---------------------------------------------------------------------------
// index dtype sniff + normalize (edge_index may be int32 or int64 on device)
// ---------------------------------------------------------------------------
__global__ void detect_kernel(const int* __restrict__ ei, int E) {
    __shared__ int any;
    if (threadIdx.x == 0) any = 0;
    __syncthreads();
    int cnt = E < 4096 ? E : 4096;
    for (int i = threadIdx.x; i < cnt; i += blockDim.x)
        if (ei[2 * i + 1] != 0) any = 1;
    __syncthreads();
    if (threadIdx.x == 0) g_is64 = any ? 0 : 1;
}

__global__ void convert_kernel(const void* __restrict__ ei, int* __restrict__ out, int total) {
    int i = blockIdx.x * blockDim.x + threadIdx.x;
    if (i >= total) return;
    if (g_is64) out[i] = (int)((const long long*)ei)[i];
    else        out[i] = ((const int*)ei)[i];
}

__global__ void deg_kernel(const int* __restrict__ dst, int* __restrict__ cnt, int E) {
    int e = blockIdx.x * blockDim.x + threadIdx.x;
    if (e < E) atomicAdd(&cnt[dst[e]], 1);
}

__global__ void invdeg_kernel(const int* __restrict__ cnt, float* __restrict__ invd, int n) {
    int i = blockIdx.x * blockDim.x + threadIdx.x;
    if (i < n) {
        int c = cnt[i];
        invd[i] = 1.0f / (float)(c > 1 ? c : 1);
    }
}

// warp per edge, float4 RED
__global__ void aggregate_kernel(const float* __restrict__ feat,
                                 const int* __restrict__ src,
                                 const int* __restrict__ dst,
                                 float* __restrict__ agg, int E) {
    int w    = (int)((blockIdx.x * (size_t)blockDim.x + threadIdx.x) >> 5);
    int lane = threadIdx.x & 31;
    if (w >= E) return;
    int s = src[w];
    int d = dst[w];
    const float4 v = *(const float4*)&feat[(size_t)s * D128 + lane * 4];
    float* p = &agg[(size_t)d * D128 + lane * 4];
    asm volatile("red.global.add.v4.f32 [%0], {%1,%2,%3,%4};"
                 :: "l"(p), "f"(v.x), "f"(v.y), "f"(v.z), "f"(v.w) : "memory");
}

// ---------------------------------------------------------------------------
// temporal weight fold (Wcat [384,128] fp32)
// ---------------------------------------------------------------------------
__global__ void wcombine_kernel(const float* __restrict__ W0,
                                const float* __restrict__ Wp,
                                const float* __restrict__ WT,
                                float* __restrict__ Wcat) {
    int row = blockIdx.x;
    int m   = blockIdx.y;
    int col = threadIdx.x;
    __shared__ float L[128];
    const float* Lsrc = (m == 0) ? W0 : (Wp + (size_t)(m - 1) * 128 * 128);
    L[col] = Lsrc[row * 128 + col];
    __syncthreads();
    float s = 0.f;
#pragma unroll 8
    for (int k = 0; k < 128; k++)
        s = fmaf(L[k], WT[(size_t)(128 + k) * 128 + col], s);
    s *= (1.0f / 3.0f);
    if (m == 0) s += WT[(size_t)row * 128 + col];
    Wcat[(size_t)(m * 128 + row) * 128 + col] = s;
}

// ---------------------------------------------------------------------------
// bake W [K,128] fp32 -> Bt[n][k] bf16 (hi image at 0, lo image at 128*K)
// ---------------------------------------------------------------------------
__global__ void wprep_kernel(const float* __restrict__ W, uint16_t* __restrict__ img, int K) {
    int idx = blockIdx.x * blockDim.x + threadIdx.x;
    if (idx >= 128 * K) return;
    int nn = idx / K, k = idx % K;
    float x = W[(size_t)k * 128 + nn];
    __nv_bfloat16 h = __float2bfloat16_rn(x);
    float hf = __bfloat162float(h);
    __nv_bfloat16 l = __float2bfloat16_rn(x - hf);
    img[(size_t)nn * K + k]                    = *(uint16_t*)&h;
    img[(size_t)128 * K + (size_t)nn * K + k]  = *(uint16_t*)&l;
}

// ---------------------------------------------------------------------------
// SAGE layer GEMM (tensor): OUT = relu([H | AGG*invd] @ W), K=256
// block: 128x128 tile, 256 thr, 8 warps (4 m x 2 n), warp tile 32x64
// ---------------------------------------------------------------------------
__global__ __launch_bounds__(256, 1)
void gemm_sage_mma(const float* __restrict__ H, const float* __restrict__ AGG,
                   const float* __restrict__ invd, const uint16_t* __restrict__ Bt,
                   float* __restrict__ OUT, float* __restrict__ tail,
                   int n, int numTail) {
    __shared__ __align__(16) uint16_t As_hi[2][128][16];
    __shared__ __align__(16) uint16_t As_lo[2][128][16];
    __shared__ __align__(16) uint16_t Bs_hi[2][128][16];
    __shared__ __align__(16) uint16_t Bs_lo[2][128][16];

    const int K = 256;
    const int tid  = threadIdx.x;
    const int lane = tid & 31;
    const int wid  = tid >> 5;
    const int wm   = wid & 3;           // 0..3: rows wm*32..+31
    const int wn   = wid >> 2;          // 0..1: cols wn*64..+63
    const int rowBase = blockIdx.x * 128;

    // staging assignment: thread t -> row t>>1, k-halves (t&1)*8
    const int arow = tid >> 1;
    const int koff = (tid & 1) * 8;
    const int grow = rowBase + arow;
    const bool rv  = grow < n;
    const float myinv = rv ? invd[grow] : 0.f;
    const float* hptr = H   + (size_t)(rv ? grow : 0) * D128;
    const float* aptr = AGG + (size_t)(rv ? grow : 0) * D128;
    const size_t bbase = (size_t)arow * K;        // Bt row (n = arow)

    float acc[2][8][4];
#pragma unroll
    for (int mt = 0; mt < 2; mt++)
#pragma unroll
        for (int nt = 0; nt < 8; nt++)
#pragma unroll
            for (int q = 0; q < 4; q++) acc[mt][nt][q] = 0.f;

    float4 pa, pb;
    uint4  pbh, pbl;
    // prefetch kstep 0
    {
        pa = rv ? *(const float4*)&hptr[koff]     : make_float4(0, 0, 0, 0);
        pb = rv ? *(const float4*)&hptr[koff + 4] : make_float4(0, 0, 0, 0);
        pbh = *(const uint4*)&Bt[bbase + koff];
        pbl = *(const uint4*)&Bt[(size_t)128 * K + bbase + koff];
    }

    int stage = 0;
    const int NK = K / 16;
#pragma unroll 1
    for (int ks = 0; ks < NK; ks++) {
        // store staged regs -> smem
        {
            uint32_t h0, l0, h1, l1, h2, l2, h3, l3;
            split2(pa.x, pa.y, h0, l0);
            split2(pa.z, pa.w, h1, l1);
            split2(pb.x, pb.y, h2, l2);
            split2(pb.z, pb.w, h3, l3);
            *(uint4*)&As_hi[stage][arow][koff] = make_uint4(h0, h1, h2, h3);
            *(uint4*)&As_lo[stage][arow][koff] = make_uint4(l0, l1, l2, l3);
            *(uint4*)&Bs_hi[stage][arow][koff] = pbh;
            *(uint4*)&Bs_lo[stage][arow][koff] = pbl;
        }
        __syncthreads();
        // prefetch next kstep
        if (ks + 1 < NK) {
            int kb = (ks + 1) * 16;
            if (rv) {
                if (kb < 128) {
                    pa = *(const float4*)&hptr[kb + koff];
                    pb = *(const float4*)&hptr[kb + koff + 4];
                } else {
                    float4 t0 = *(const float4*)&aptr[kb - 128 + koff];
                    float4 t1 = *(const float4*)&aptr[kb - 128 + koff + 4];
                    pa = make_float4(t0.x * myinv, t0.y * myinv, t0.z * myinv, t0.w * myinv);
                    pb = make_float4(t1.x * myinv, t1.y * myinv, t1.z * myinv, t1.w * myinv);
                }
            }
            pbh = *(const uint4*)&Bt[bbase + kb + koff];
            pbl = *(const uint4*)&Bt[(size_t)128 * K + bbase + kb + koff];
        }
        // compute from smem[stage]
        {
            const int r  = lane >> 2;
            const int c2 = (lane & 3) * 2;
            uint32_t bh[8][2], bl[8][2];
#pragma unroll
            for (int nt = 0; nt < 8; nt++) {
                int nn = wn * 64 + nt * 8 + r;
                bh[nt][0] = *(const uint32_t*)&Bs_hi[stage][nn][c2];
                bh[nt][1] = *(const uint32_t*)&Bs_hi[stage][nn][c2 + 8];
                bl[nt][0] = *(const uint32_t*)&Bs_lo[stage][nn][c2];
                bl[nt][1] = *(const uint32_t*)&Bs_lo[stage][nn][c2 + 8];
            }
#pragma unroll
            for (int mt = 0; mt < 2; mt++) {
                int r0 = wm * 32 + mt * 16;
                uint32_t ah[4], al[4];
                ah[0] = *(const uint32_t*)&As_hi[stage][r0 + r][c2];
                ah[1] = *(const uint32_t*)&As_hi[stage][r0 + r + 8][c2];
                ah[2] = *(const uint32_t*)&As_hi[stage][r0 + r][c2 + 8];
                ah[3] = *(const uint32_t*)&As_hi[stage][r0 + r + 8][c2 + 8];
                al[0] = *(const uint32_t*)&As_lo[stage][r0 + r][c2];
                al[1] = *(const uint32_t*)&As_lo[stage][r0 + r + 8][c2];
                al[2] = *(const uint32_t*)&As_lo[stage][r0 + r][c2 + 8];
                al[3] = *(const uint32_t*)&As_lo[stage][r0 + r + 8][c2 + 8];
#pragma unroll
                for (int nt = 0; nt < 8; nt++) {
                    mma16816(acc[mt][nt], ah, bh[nt]);
                    mma16816(acc[mt][nt], ah, bl[nt]);
                    mma16816(acc[mt][nt], al, bh[nt]);
                }
            }
        }
        stage ^= 1;
    }

    // epilogue: relu + store (+ tail copy)
    const int r  = lane >> 2;
    const int c2 = (lane & 3) * 2;
#pragma unroll
    for (int mt = 0; mt < 2; mt++) {
#pragma unroll
        for (int half = 0; half < 2; half++) {
            int row = rowBase + wm * 32 + mt * 16 + half * 8 + r;
            if (row >= n) continue;
#pragma unroll
            for (int nt = 0; nt < 8; nt++) {
                int col = wn * 64 + nt * 8 + c2;
                float2 o;
                o.x = fmaxf(acc[mt][nt][half * 2 + 0], 0.f);
                o.y = fmaxf(acc[mt][nt][half * 2 + 1], 0.f);
                *(float2*)&OUT[(size_t)row * D128 + col] = o;
                if (tail != nullptr && row >= numTail)
                    *(float2*)&tail[(size_t)row * D128 + col] = o;
            }
        }
    }
}

// ---------------------------------------------------------------------------
// final fused GEMM (tensor): f = leakyrelu([F2|P0|P1] @ Wcat, 0.2)
//                            out = f / max(||f||, 1e-12) ;  K = 384
// ---------------------------------------------------------------------------
__global__ __launch_bounds__(256, 1)
void gemm_final_mma(const float* __restrict__ F2, const float* __restrict__ P0,
                    const float* __restrict__ P1, const uint16_t* __restrict__ Bt,
                    float* __restrict__ OUT, int num) {
    __shared__ __align__(16) uint16_t As_hi[2][128][16];
    __shared__ __align__(16) uint16_t As_lo[2][128][16];
    __shared__ __align__(16) uint16_t Bs_hi[2][128][16];
    __shared__ __align__(16) uint16_t Bs_lo[2][128][16];
    __shared__ float ssbuf[2][128];

    const int K = 384;
    const int tid  = threadIdx.x;
    const int lane = tid & 31;
    const int wid  = tid >> 5;
    const int wm   = wid & 3;
    const int wn   = wid >> 2;
    const int rowBase = blockIdx.x * 128;

    const int arow = tid >> 1;
    const int koff = (tid & 1) * 8;
    const int grow = rowBase + arow;
    const bool rv  = grow < num;
    const size_t ro = (size_t)(rv ? grow : 0) * D128;
    const size_t bbase = (size_t)arow * K;

    float acc[2][8][4];
#pragma unroll
    for (int mt = 0; mt < 2; mt++)
#pragma unroll
        for (int nt = 0; nt < 8; nt++)
#pragma unroll
            for (int q = 0; q < 4; q++) acc[mt][nt][q] = 0.f;

    float4 pa, pb;
    uint4  pbh, pbl;
    {
        pa = rv ? *(const float4*)&F2[ro + koff]     : make_float4(0, 0, 0, 0);
        pb = rv ? *(const float4*)&F2[ro + koff + 4] : make_float4(0, 0, 0, 0);
        pbh = *(const uint4*)&Bt[bbase + koff];
        pbl = *(const uint4*)&Bt[(size_t)128 * K + bbase + koff];
    }

    int stage = 0;
    const int NK = K / 16;
#pragma unroll 1
    for (int ks = 0; ks < NK; ks++) {
        {
            uint32_t h0, l0, h1, l1, h2, l2, h3, l3;
            split2(pa.x, pa.y, h0, l0);
            split2(pa.z, pa.w, h1, l1);
            split2(pb.x, pb.y, h2, l2);
            split2(pb.z, pb.w, h3, l3);
            *(uint4*)&As_hi[stage][arow][koff] = make_uint4(h0, h1, h2, h3);
            *(uint4*)&As_lo[stage][arow][koff] = make_uint4(l0, l1, l2, l3);
            *(uint4*)&Bs_hi[stage][arow][koff] = pbh;
            *(uint4*)&Bs_lo[stage][arow][koff] = pbl;
        }
        __syncthreads();
        if (ks + 1 < NK) {
            int kb = (ks + 1) * 16;
            if (rv) {
                const float* s = (kb < 128) ? (F2 + ro + kb)
                               : (kb < 256) ? (P0 + ro + kb - 128)
                                            : (P1 + ro + kb - 256);
                pa = *(const float4*)&s[koff];
                pb = *(const float4*)&s[koff + 4];
            }
            pbh = *(const uint4*)&Bt[bbase + kb + koff];
            pbl = *(const uint4*)&Bt[(size_t)128 * K + bbase + kb + koff];
        }
        {
            const int r  = lane >> 2;
            const int c2 = (lane & 3) * 2;
            uint32_t bh[8][2], bl[8][2];
#pragma unroll
            for (int nt = 0; nt < 8; nt++) {
                int nn = wn * 64 + nt * 8 + r;
                bh[nt][0] = *(const uint32_t*)&Bs_hi[stage][nn][c2];
                bh[nt][1] = *(const uint32_t*)&Bs_hi[stage][nn][c2 + 8];
                bl[nt][0] = *(const uint32_t*)&Bs_lo[stage][nn][c2];
                bl[nt][1] = *(const uint32_t*)&Bs_lo[stage][nn][c2 + 8];
            }
#pragma unroll
            for (int mt = 0; mt < 2; mt++) {
                int r0 = wm * 32 + mt * 16;
                uint32_t ah[4], al[4];
                ah[0] = *(const uint32_t*)&As_hi[stage][r0 + r][c2];
                ah[1] = *(const uint32_t*)&As_hi[stage][r0 + r + 8][c2];
                ah[2] = *(const uint32_t*)&As_hi[stage][r0 + r][c2 + 8];
                ah[3] = *(const uint32_t*)&As_hi[stage][r0 + r + 8][c2 + 8];
                al[0] = *(const uint32_t*)&As_lo[stage][r0 + r][c2];
                al[1] = *(const uint32_t*)&As_lo[stage][r0 + r + 8][c2];
                al[2] = *(const uint32_t*)&As_lo[stage][r0 + r][c2 + 8];
                al[3] = *(const uint32_t*)&As_lo[stage][r0 + r + 8][c2 + 8];
#pragma unroll
                for (int nt = 0; nt < 8; nt++) {
                    mma16816(acc[mt][nt], ah, bh[nt]);
                    mma16816(acc[mt][nt], ah, bl[nt]);
                    mma16816(acc[mt][nt], al, bh[nt]);
                }
            }
        }
        stage ^= 1;
    }

    // leaky relu in-place + partial row sums of squares
    const int r  = lane >> 2;
    float ss[2][2] = {{0.f, 0.f}, {0.f, 0.f}};
#pragma unroll
    for (int mt = 0; mt < 2; mt++)
#pragma unroll
        for (int nt = 0; nt < 8; nt++)
#pragma unroll
            for (int q = 0; q < 4; q++) {
                float v = acc[mt][nt][q];
                v = (v > 0.f) ? v : 0.2f * v;
                acc[mt][nt][q] = v;
                ss[mt][q >> 1] = fmaf(v, v, ss[mt][q >> 1]);
            }
    // reduce across the 4 lanes sharing a row (xor 1, 2)
#pragma unroll
    for (int m = 1; m < 4; m <<= 1) {
#pragma unroll
        for (int mt = 0; mt < 2; mt++) {
            ss[mt][0] += __shfl_xor_sync(0xffffffffu, ss[mt][0], m);
            ss[mt][1] += __shfl_xor_sync(0xffffffffu, ss[mt][1], m);
        }
    }
    // cross warp_n reduction via smem
    if ((lane & 3) == 0) {
#pragma unroll
        for (int mt = 0; mt < 2; mt++)
#pragma unroll
            for (int half = 0; half < 2; half++)
                ssbuf[wn][wm * 32 + mt * 16 + half * 8 + r] = ss[mt][half];
    }
    __syncthreads();

    const int c2 = (lane & 3) * 2;
#pragma unroll
    for (int mt = 0; mt < 2; mt++) {
#pragma unroll
        for (int half = 0; half < 2; half++) {
            int rl  = wm * 32 + mt * 16 + half * 8 + r;
            int row = rowBase + rl;
            if (row >= num) continue;
            float tot = ssbuf[0][rl] + ssbuf[1][rl];
            float inv = 1.0f / fmaxf(sqrtf(tot), 1e-12f);
#pragma unroll
            for (int nt = 0; nt < 8; nt++) {
                int col = wn * 64 + nt * 8 + c2;
                float2 o;
                o.x = acc[mt][nt][half * 2 + 0] * inv;
                o.y = acc[mt][nt][half * 2 + 1] * inv;
                *(float2*)&OUT[(size_t)row * D128 + col] = o;
            }
        }
    }
}

// ---------------------------------------------------------------------------
// launch
// ---------------------------------------------------------------------------
extern "C" void kernel_launch(void* const* d_in, const int* in_sizes, int n_in,
                              void* d_out, int out_size) {
    const float* x    = (const float*)d_in[0];
    const float* past = (const float*)d_in[1];
    const float* W1   = (const float*)d_in[2];
    const float* W2   = (const float*)d_in[3];
    const float* W0   = (const float*)d_in[4];
    const float* Wp   = (const float*)d_in[5];
    const float* WT   = (const float*)d_in[6];
    const void*  ei   = d_in[7];
    float*       out  = (float*)d_out;

    const int n   = in_sizes[0] / D128;
    const int num = in_sizes[1] / (2 * D128);
    const int E   = in_sizes[7] / 2;

    const float* p0 = past;
    const float* p1 = past + (size_t)num * D128;

    float *agg, *feat1, *feat2, *invd, *Wcat;
    int *cnt, *idx;
    uint16_t *B1, *B2, *Bf;
    cudaGetSymbolAddress((void**)&agg,   g_agg);
    cudaGetSymbolAddress((void**)&feat1, g_feat1);
    cudaGetSymbolAddress((void**)&feat2, g_feat2);
    cudaGetSymbolAddress((void**)&invd,  g_invdeg);
    cudaGetSymbolAddress((void**)&cnt,   g_cnt);
    cudaGetSymbolAddress((void**)&Wcat,  g_Wcat);
    cudaGetSymbolAddress((void**)&idx,   g_idx);
    cudaGetSymbolAddress((void**)&B1,    g_B1);
    cudaGetSymbolAddress((void**)&B2,    g_B2);
    cudaGetSymbolAddress((void**)&Bf,    g_Bf);

    const int* src = idx;
    const int* dst = idx + E;
    const size_t featBytes = (size_t)n * D128 * sizeof(float);

    // index normalize + degrees
    detect_kernel<<<1, 256>>>((const int*)ei, E);
    convert_kernel<<<(2 * E + 255) / 256, 256>>>(ei, idx, 2 * E);
    cudaMemsetAsync(cnt, 0, (size_t)n * sizeof(int));
    cudaMemsetAsync(agg, 0, featBytes);
    deg_kernel<<<(E + 255) / 256, 256>>>(dst, cnt, E);
    invdeg_kernel<<<(n + 255) / 256, 256>>>(cnt, invd, n);

    // bake transposed hi/lo weight images
    wprep_kernel<<<(128 * 256 + 255) / 256, 256>>>(W1, B1, 256);
    wprep_kernel<<<(128 * 256 + 255) / 256, 256>>>(W2, B2, 256);
    {
        dim3 g(128, 3);
        wcombine_kernel<<<g, 128>>>(W0, Wp, WT, Wcat);
    }
    wprep_kernel<<<(128 * 384 + 255) / 256, 256>>>(Wcat, Bf, 384);

    const int aggBlocks  = (E + 7) / 8;
    const int gemmBlocks = (n + 127) / 128;

    // layer 1
    aggregate_kernel<<<aggBlocks, 256>>>(x, src, dst, agg, E);
    gemm_sage_mma<<<gemmBlocks, 256>>>(x, agg, invd, B1, feat1, nullptr, n, n);

    // layer 2 (tail rows >= num stream into d_out)
    cudaMemsetAsync(agg, 0, featBytes);
    aggregate_kernel<<<aggBlocks, 256>>>(feat1, src, dst, agg, E);
    gemm_sage_mma<<<gemmBlocks, 256>>>(feat1, agg, invd, B2, feat2, out, n, num);

    // fused final
    gemm_final_mma<<<(num + 127) / 128, 256>>>(feat2, p0, p1, Bf, out, num);
}

// round 5
// speedup vs baseline: 1.5828x; 1.2766x over previous
#include <cuda_runtime.h>
#include <cuda_bf16.h>
#include <cstddef>
#include <cstdint>

// ---------------------------------------------------------------------------
// dygraphSAGE on GB300 (base sm_103 target): CSR-gather aggregation +
// mma.sync bf16 hi/lo GEMMs, temporal weights folded into one [384,128] GEMM
// ---------------------------------------------------------------------------

#define D128 128
#define MAXN 131072
#define MAXE 2097152

// scratch (device globals -- allocation-free per harness rules)
__device__ float g_agg  [(size_t)MAXN * D128];
__device__ float g_feat1[(size_t)MAXN * D128];
__device__ float g_feat2[(size_t)MAXN * D128];
__device__ int   g_cnt[MAXN];
__device__ int   g_off[MAXN];
__device__ int   g_cursor[MAXN];
__device__ int   g_adj[MAXE];
__device__ float g_Wcat[384 * D128];
__device__ int   g_idx[2 * MAXE];
__device__ int   g_is64;
// pre-baked transposed weights Bt[n][k] bf16, hi image then lo image
__device__ __align__(16) uint16_t g_B1[2 * 128 * 256];
__device__ __align__(16) uint16_t g_B2[2 * 128 * 256];
__device__ __align__(16) uint16_t g_Bf[2 * 128 * 384];

// ---------------------------------------------------------------------------
// helpers
// ---------------------------------------------------------------------------
__device__ __forceinline__ void split2(float x0, float x1, uint32_t& hi, uint32_t& lo) {
    asm("cvt.rn.bf16x2.f32 %0, %1, %2;" : "=r"(hi) : "f"(x1), "f"(x0));
    float h0 = __uint_as_float(hi << 16);
    float h1 = __uint_as_float(hi & 0xffff0000u);
    asm("cvt.rn.bf16x2.f32 %0, %1, %2;" : "=r"(lo) : "f"(x1 - h1), "f"(x0 - h0));
}

__device__ __forceinline__ void mma16816(float* c, const uint32_t* a, const uint32_t* b) {
    asm volatile("mma.sync.aligned.m16n8k16.row.col.f32.bf16.bf16.f32 "
                 "{%0,%1,%2,%3}, {%4,%5,%6,%7}, {%8,%9}, {%0,%1,%2,%3};"
                 : "+f"(c[0]), "+f"(c[1]), "+f"(c[2]), "+f"(c[3])
                 : "r"(a[0]), "r"(a[1]), "r"(a[2]), "r"(a[3]),
                   "r"(b[0]), "r"(b[1]));
}

// ---------------------------------------------------------------------------
// index dtype sniff + normalize
// ---------------------------------------------------------------------------
__global__ void detect_kernel(const int* __restrict__ ei, int E) {
    __shared__ int any;
    if (threadIdx.x == 0) any = 0;
    __syncthreads();
    int cnt = E < 4096 ? E : 4096;
    for (int i = threadIdx.x; i < cnt; i += blockDim.x)
        if (ei[2 * i + 1] != 0) any = 1;
    __syncthreads();
    if (threadIdx.x == 0) g_is64 = any ? 0 : 1;
}

__global__ void convert_kernel(const void* __restrict__ ei, int* __restrict__ out, int total) {
    int i = blockIdx.x * blockDim.x + threadIdx.x;
    if (i >= total) return;
    if (g_is64) out[i] = (int)((const long long*)ei)[i];
    else        out[i] = ((const int*)ei)[i];
}

__global__ void deg_kernel(const int* __restrict__ dst, int* __restrict__ cnt, int E) {
    int e = blockIdx.x * blockDim.x + threadIdx.x;
    if (e < E) atomicAdd(&cnt[dst[e]], 1);
}

// ---------------------------------------------------------------------------
// single-block exclusive scan of cnt -> off (and cursor copy)
// ---------------------------------------------------------------------------
__global__ void scan_kernel(const int* __restrict__ cnt, int* __restrict__ off,
                            int* __restrict__ cursor, int n) {
    __shared__ int sums[1024];
    const int tid = threadIdx.x;
    const int chunk = (n + 1023) / 1024;
    const int s0 = tid * chunk;
    const int s1 = (s0 + chunk < n) ? s0 + chunk : n;
    int local = 0;
    for (int i = s0; i < s1; i++) local += cnt[i];
    sums[tid] = local;
    __syncthreads();
    // Hillis-Steele inclusive scan
    for (int d = 1; d < 1024; d <<= 1) {
        int t = (tid >= d) ? sums[tid - d] : 0;
        __syncthreads();
        sums[tid] += t;
        __syncthreads();
    }
    int run = sums[tid] - local;   // exclusive base for this thread's chunk
    for (int i = s0; i < s1; i++) {
        off[i] = run;
        cursor[i] = run;
        run += cnt[i];
    }
}

__global__ void scatter_kernel(const int* __restrict__ src, const int* __restrict__ dst,
                               int* __restrict__ cursor, int* __restrict__ adj, int E) {
    int e = blockIdx.x * blockDim.x + threadIdx.x;
    if (e >= E) return;
    int pos = atomicAdd(&cursor[dst[e]], 1);
    adj[pos] = src[e];
}

// ---------------------------------------------------------------------------
// CSR gather mean-aggregation: one warp per node, lane owns 4 features.
// Writes agg already scaled by 1/max(deg,1).
// ---------------------------------------------------------------------------
__global__ __launch_bounds__(256)
void gather_kernel(const float* __restrict__ feat, const int* __restrict__ adj,
                   const int* __restrict__ off, const int* __restrict__ cnt,
                   float* __restrict__ agg, int n) {
    int w    = (int)((blockIdx.x * (size_t)blockDim.x + threadIdx.x) >> 5);
    int lane = threadIdx.x & 31;
    if (w >= n) return;
    const int start = off[w];
    const int deg   = cnt[w];
    float ax = 0.f, ay = 0.f, az = 0.f, aw = 0.f;
    int i = 0;
    for (; i + 4 <= deg; i += 4) {
        int s0 = adj[start + i + 0];
        int s1 = adj[start + i + 1];
        int s2 = adj[start + i + 2];
        int s3 = adj[start + i + 3];
        float4 v0 = *(const float4*)&feat[(size_t)s0 * D128 + lane * 4];
        float4 v1 = *(const float4*)&feat[(size_t)s1 * D128 + lane * 4];
        float4 v2 = *(const float4*)&feat[(size_t)s2 * D128 + lane * 4];
        float4 v3 = *(const float4*)&feat[(size_t)s3 * D128 + lane * 4];
        ax += (v0.x + v1.x) + (v2.x + v3.x);
        ay += (v0.y + v1.y) + (v2.y + v3.y);
        az += (v0.z + v1.z) + (v2.z + v3.z);
        aw += (v0.w + v1.w) + (v2.w + v3.w);
    }
    for (; i < deg; i++) {
        int s = adj[start + i];
        float4 v = *(const float4*)&feat[(size_t)s * D128 + lane * 4];
        ax += v.x; ay += v.y; az += v.z; aw += v.w;
    }
    float sc = 1.0f / (float)(deg > 1 ? deg : 1);
    float4 o = make_float4(ax * sc, ay * sc, az * sc, aw * sc);
    *(float4*)&agg[(size_t)w * D128 + lane * 4] = o;
}

// ---------------------------------------------------------------------------
// temporal weight fold (Wcat [384,128] fp32)
// ---------------------------------------------------------------------------
__global__ void wcombine_kernel(const float* __restrict__ W0,
                                const float* __restrict__ Wp,
                                const float* __restrict__ WT,
                                float* __restrict__ Wcat) {
    int row = blockIdx.x;
    int m   = blockIdx.y;
    int col = threadIdx.x;
    __shared__ float L[128];
    const float* Lsrc = (m == 0) ? W0 : (Wp + (size_t)(m - 1) * 128 * 128);
    L[col] = Lsrc[row * 128 + col];
    __syncthreads();
    float s = 0.f;
#pragma unroll 8
    for (int k = 0; k < 128; k++)
        s = fmaf(L[k], WT[(size_t)(128 + k) * 128 + col], s);
    s *= (1.0f / 3.0f);
    if (m == 0) s += WT[(size_t)row * 128 + col];
    Wcat[(size_t)(m * 128 + row) * 128 + col] = s;
}

// ---------------------------------------------------------------------------
// bake W [K,128] fp32 -> Bt[n][k] bf16 (hi image at 0, lo image at 128*K)
// ---------------------------------------------------------------------------
__global__ void wprep_kernel(const float* __restrict__ W, uint16_t* __restrict__ img, int K) {
    int idx = blockIdx.x * blockDim.x + threadIdx.x;
    if (idx >= 128 * K) return;
    int nn = idx / K, k = idx % K;
    float x = W[(size_t)k * 128 + nn];
    __nv_bfloat16 h = __float2bfloat16_rn(x);
    float hf = __bfloat162float(h);
    __nv_bfloat16 l = __float2bfloat16_rn(x - hf);
    img[(size_t)nn * K + k]                    = *(uint16_t*)&h;
    img[(size_t)128 * K + (size_t)nn * K + k]  = *(uint16_t*)&l;
}

// ---------------------------------------------------------------------------
// SAGE layer GEMM (tensor): OUT = relu([H | AGG] @ W), K=256, AGG pre-scaled
// block: 128x128 tile, 256 thr, 8 warps (4 m x 2 n), warp tile 32x64
// ---------------------------------------------------------------------------
__global__ __launch_bounds__(256, 1)
void gemm_sage_mma(const float* __restrict__ H, const float* __restrict__ AGG,
                   const uint16_t* __restrict__ Bt,
                   float* __restrict__ OUT, float* __restrict__ tail,
                   int n, int numTail) {
    __shared__ __align__(16) uint16_t As_hi[2][128][16];
    __shared__ __align__(16) uint16_t As_lo[2][128][16];
    __shared__ __align__(16) uint16_t Bs_hi[2][128][16];
    __shared__ __align__(16) uint16_t Bs_lo[2][128][16];

    const int K = 256;
    const int tid  = threadIdx.x;
    const int lane = tid & 31;
    const int wid  = tid >> 5;
    const int wm   = wid & 3;
    const int wn   = wid >> 2;
    const int rowBase = blockIdx.x * 128;

    const int arow = tid >> 1;
    const int koff = (tid & 1) * 8;
    const int grow = rowBase + arow;
    const bool rv  = grow < n;
    const float* hptr = H   + (size_t)(rv ? grow : 0) * D128;
    const float* aptr = AGG + (size_t)(rv ? grow : 0) * D128;
    const size_t bbase = (size_t)arow * K;

    float acc[2][8][4];
#pragma unroll
    for (int mt = 0; mt < 2; mt++)
#pragma unroll
        for (int nt = 0; nt < 8; nt++)
#pragma unroll
            for (int q = 0; q < 4; q++) acc[mt][nt][q] = 0.f;

    float4 pa, pb;
    uint4  pbh, pbl;
    {
        pa = rv ? *(const float4*)&hptr[koff]     : make_float4(0, 0, 0, 0);
        pb = rv ? *(const float4*)&hptr[koff + 4] : make_float4(0, 0, 0, 0);
        pbh = *(const uint4*)&Bt[bbase + koff];
        pbl = *(const uint4*)&Bt[(size_t)128 * K + bbase + koff];
    }

    int stage = 0;
    const int NK = K / 16;
#pragma unroll 1
    for (int ks = 0; ks < NK; ks++) {
        {
            uint32_t h0, l0, h1, l1, h2, l2, h3, l3;
            split2(pa.x, pa.y, h0, l0);
            split2(pa.z, pa.w, h1, l1);
            split2(pb.x, pb.y, h2, l2);
            split2(pb.z, pb.w, h3, l3);
            *(uint4*)&As_hi[stage][arow][koff] = make_uint4(h0, h1, h2, h3);
            *(uint4*)&As_lo[stage][arow][koff] = make_uint4(l0, l1, l2, l3);
            *(uint4*)&Bs_hi[stage][arow][koff] = pbh;
            *(uint4*)&Bs_lo[stage][arow][koff] = pbl;
        }
        __syncthreads();
        if (ks + 1 < NK) {
            int kb = (ks + 1) * 16;
            if (rv) {
                const float* s = (kb < 128) ? (hptr + kb) : (aptr + kb - 128);
                pa = *(const float4*)&s[koff];
                pb = *(const float4*)&s[koff + 4];
            }
            pbh = *(const uint4*)&Bt[bbase + kb + koff];
            pbl = *(const uint4*)&Bt[(size_t)128 * K + bbase + kb + koff];
        }
        {
            const int r  = lane >> 2;
            const int c2 = (lane & 3) * 2;
            uint32_t bh[8][2], bl[8][2];
#pragma unroll
            for (int nt = 0; nt < 8; nt++) {
                int nn = wn * 64 + nt * 8 + r;
                bh[nt][0] = *(const uint32_t*)&Bs_hi[stage][nn][c2];
                bh[nt][1] = *(const uint32_t*)&Bs_hi[stage][nn][c2 + 8];
                bl[nt][0] = *(const uint32_t*)&Bs_lo[stage][nn][c2];
                bl[nt][1] = *(const uint32_t*)&Bs_lo[stage][nn][c2 + 8];
            }
#pragma unroll
            for (int mt = 0; mt < 2; mt++) {
                int r0 = wm * 32 + mt * 16;
                uint32_t ah[4], al[4];
                ah[0] = *(const uint32_t*)&As_hi[stage][r0 + r][c2];
                ah[1] = *(const uint32_t*)&As_hi[stage][r0 + r + 8][c2];
                ah[2] = *(const uint32_t*)&As_hi[stage][r0 + r][c2 + 8];
                ah[3] = *(const uint32_t*)&As_hi[stage][r0 + r + 8][c2 + 8];
                al[0] = *(const uint32_t*)&As_lo[stage][r0 + r][c2];
                al[1] = *(const uint32_t*)&As_lo[stage][r0 + r + 8][c2];
                al[2] = *(const uint32_t*)&As_lo[stage][r0 + r][c2 + 8];
                al[3] = *(const uint32_t*)&As_lo[stage][r0 + r + 8][c2 + 8];
#pragma unroll
                for (int nt = 0; nt < 8; nt++) {
                    mma16816(acc[mt][nt], ah, bh[nt]);
                    mma16816(acc[mt][nt], ah, bl[nt]);
                    mma16816(acc[mt][nt], al, bh[nt]);
                }
            }
        }
        stage ^= 1;
    }

    const int r  = lane >> 2;
    const int c2 = (lane & 3) * 2;
#pragma unroll
    for (int mt = 0; mt < 2; mt++) {
#pragma unroll
        for (int half = 0; half < 2; half++) {
            int row = rowBase + wm * 32 + mt * 16 + half * 8 + r;
            if (row >= n) continue;
#pragma unroll
            for (int nt = 0; nt < 8; nt++) {
                int col = wn * 64 + nt * 8 + c2;
                float2 o;
                o.x = fmaxf(acc[mt][nt][half * 2 + 0], 0.f);
                o.y = fmaxf(acc[mt][nt][half * 2 + 1], 0.f);
                *(float2*)&OUT[(size_t)row * D128 + col] = o;
                if (tail != nullptr && row >= numTail)
                    *(float2*)&tail[(size_t)row * D128 + col] = o;
            }
        }
    }
}

// ---------------------------------------------------------------------------
// final fused GEMM (tensor): f = leakyrelu([F2|P0|P1] @ Wcat, 0.2)
//                            out = f / max(||f||, 1e-12) ;  K = 384
// ---------------------------------------------------------------------------
__global__ __launch_bounds__(256, 1)
void gemm_final_mma(const float* __restrict__ F2, const float* __restrict__ P0,
                    const float* __restrict__ P1, const uint16_t* __restrict__ Bt,
                    float* __restrict__ OUT, int num) {
    __shared__ __align__(16) uint16_t As_hi[2][128][16];
    __shared__ __align__(16) uint16_t As_lo[2][128][16];
    __shared__ __align__(16) uint16_t Bs_hi[2][128][16];
    __shared__ __align__(16) uint16_t Bs_lo[2][128][16];
    __shared__ float ssbuf[2][128];

    const int K = 384;
    const int tid  = threadIdx.x;
    const int lane = tid & 31;
    const int wid  = tid >> 5;
    const int wm   = wid & 3;
    const int wn   = wid >> 2;
    const int rowBase = blockIdx.x * 128;

    const int arow = tid >> 1;
    const int koff = (tid & 1) * 8;
    const int grow = rowBase + arow;
    const bool rv  = grow < num;
    const size_t ro = (size_t)(rv ? grow : 0) * D128;
    const size_t bbase = (size_t)arow * K;

    float acc[2][8][4];
#pragma unroll
    for (int mt = 0; mt < 2; mt++)
#pragma unroll
        for (int nt = 0; nt < 8; nt++)
#pragma unroll
            for (int q = 0; q < 4; q++) acc[mt][nt][q] = 0.f;

    float4 pa, pb;
    uint4  pbh, pbl;
    {
        pa = rv ? *(const float4*)&F2[ro + koff]     : make_float4(0, 0, 0, 0);
        pb = rv ? *(const float4*)&F2[ro + koff + 4] : make_float4(0, 0, 0, 0);
        pbh = *(const uint4*)&Bt[bbase + koff];
        pbl = *(const uint4*)&Bt[(size_t)128 * K + bbase + koff];
    }

    int stage = 0;
    const int NK = K / 16;
#pragma unroll 1
    for (int ks = 0; ks < NK; ks++) {
        {
            uint32_t h0, l0, h1, l1, h2, l2, h3, l3;
            split2(pa.x, pa.y, h0, l0);
            split2(pa.z, pa.w, h1, l1);
            split2(pb.x, pb.y, h2, l2);
            split2(pb.z, pb.w, h3, l3);
            *(uint4*)&As_hi[stage][arow][koff] = make_uint4(h0, h1, h2, h3);
            *(uint4*)&As_lo[stage][arow][koff] = make_uint4(l0, l1, l2, l3);
            *(uint4*)&Bs_hi[stage][arow][koff] = pbh;
            *(uint4*)&Bs_lo[stage][arow][koff] = pbl;
        }
        __syncthreads();
        if (ks + 1 < NK) {
            int kb = (ks + 1) * 16;
            if (rv) {
                const float* s = (kb < 128) ? (F2 + ro + kb)
                               : (kb < 256) ? (P0 + ro + kb - 128)
                                            : (P1 + ro + kb - 256);
                pa = *(const float4*)&s[koff];
                pb = *(const float4*)&s[koff + 4];
            }
            pbh = *(const uint4*)&Bt[bbase + kb + koff];
            pbl = *(const uint4*)&Bt[(size_t)128 * K + bbase + kb + koff];
        }
        {
            const int r  = lane >> 2;
            const int c2 = (lane & 3) * 2;
            uint32_t bh[8][2], bl[8][2];
#pragma unroll
            for (int nt = 0; nt < 8; nt++) {
                int nn = wn * 64 + nt * 8 + r;
                bh[nt][0] = *(const uint32_t*)&Bs_hi[stage][nn][c2];
                bh[nt][1] = *(const uint32_t*)&Bs_hi[stage][nn][c2 + 8];
                bl[nt][0] = *(const uint32_t*)&Bs_lo[stage][nn][c2];
                bl[nt][1] = *(const uint32_t*)&Bs_lo[stage][nn][c2 + 8];
            }
#pragma unroll
            for (int mt = 0; mt < 2; mt++) {
                int r0 = wm * 32 + mt * 16;
                uint32_t ah[4], al[4];
                ah[0] = *(const uint32_t*)&As_hi[stage][r0 + r][c2];
                ah[1] = *(const uint32_t*)&As_hi[stage][r0 + r + 8][c2];
                ah[2] = *(const uint32_t*)&As_hi[stage][r0 + r][c2 + 8];
                ah[3] = *(const uint32_t*)&As_hi[stage][r0 + r + 8][c2 + 8];
                al[0] = *(const uint32_t*)&As_lo[stage][r0 + r][c2];
                al[1] = *(const uint32_t*)&As_lo[stage][r0 + r + 8][c2];
                al[2] = *(const uint32_t*)&As_lo[stage][r0 + r][c2 + 8];
                al[3] = *(const uint32_t*)&As_lo[stage][r0 + r + 8][c2 + 8];
#pragma unroll
                for (int nt = 0; nt < 8; nt++) {
                    mma16816(acc[mt][nt], ah, bh[nt]);
                    mma16816(acc[mt][nt], ah, bl[nt]);
                    mma16816(acc[mt][nt], al, bh[nt]);
                }
            }
        }
        stage ^= 1;
    }

    const int r  = lane >> 2;
    float ss[2][2] = {{0.f, 0.f}, {0.f, 0.f}};
#pragma unroll
    for (int mt = 0; mt < 2; mt++)
#pragma unroll
        for (int nt = 0; nt < 8; nt++)
#pragma unroll
            for (int q = 0; q < 4; q++) {
                float v = acc[mt][nt][q];
                v = (v > 0.f) ? v : 0.2f * v;
                acc[mt][nt][q] = v;
                ss[mt][q >> 1] = fmaf(v, v, ss[mt][q >> 1]);
            }
#pragma unroll
    for (int m = 1; m < 4; m <<= 1) {
#pragma unroll
        for (int mt = 0; mt < 2; mt++) {
            ss[mt][0] += __shfl_xor_sync(0xffffffffu, ss[mt][0], m);
            ss[mt][1] += __shfl_xor_sync(0xffffffffu, ss[mt][1], m);
        }
    }
    if ((lane & 3) == 0) {
#pragma unroll
        for (int mt = 0; mt < 2; mt++)
#pragma unroll
            for (int half = 0; half < 2; half++)
                ssbuf[wn][wm * 32 + mt * 16 + half * 8 + r] = ss[mt][half];
    }
    __syncthreads();

    const int c2 = (lane & 3) * 2;
#pragma unroll
    for (int mt = 0; mt < 2; mt++) {
#pragma unroll
        for (int half = 0; half < 2; half++) {
            int rl  = wm * 32 + mt * 16 + half * 8 + r;
            int row = rowBase + rl;
            if (row >= num) continue;
            float tot = ssbuf[0][rl] + ssbuf[1][rl];
            float inv = 1.0f / fmaxf(sqrtf(tot), 1e-12f);
#pragma unroll
            for (int nt = 0; nt < 8; nt++) {
                int col = wn * 64 + nt * 8 + c2;
                float2 o;
                o.x = acc[mt][nt][half * 2 + 0] * inv;
                o.y = acc[mt][nt][half * 2 + 1] * inv;
                *(float2*)&OUT[(size_t)row * D128 + col] = o;
            }
        }
    }
}

// ---------------------------------------------------------------------------
// launch
// ---------------------------------------------------------------------------
extern "C" void kernel_launch(void* const* d_in, const int* in_sizes, int n_in,
                              void* d_out, int out_size) {
    const float* x    = (const float*)d_in[0];
    const float* past = (const float*)d_in[1];
    const float* W1   = (const float*)d_in[2];
    const float* W2   = (const float*)d_in[3];
    const float* W0   = (const float*)d_in[4];
    const float* Wp   = (const float*)d_in[5];
    const float* WT   = (const float*)d_in[6];
    const void*  ei   = d_in[7];
    float*       out  = (float*)d_out;

    const int n   = in_sizes[0] / D128;
    const int num = in_sizes[1] / (2 * D128);
    const int E   = in_sizes[7] / 2;

    const float* p0 = past;
    const float* p1 = past + (size_t)num * D128;

    float *agg, *feat1, *feat2, *Wcat;
    int *cnt, *off, *cursor, *adj, *idx;
    uint16_t *B1, *B2, *Bf;
    cudaGetSymbolAddress((void**)&agg,    g_agg);
    cudaGetSymbolAddress((void**)&feat1,  g_feat1);
    cudaGetSymbolAddress((void**)&feat2,  g_feat2);
    cudaGetSymbolAddress((void**)&cnt,    g_cnt);
    cudaGetSymbolAddress((void**)&off,    g_off);
    cudaGetSymbolAddress((void**)&cursor, g_cursor);
    cudaGetSymbolAddress((void**)&adj,    g_adj);
    cudaGetSymbolAddress((void**)&Wcat,   g_Wcat);
    cudaGetSymbolAddress((void**)&idx,    g_idx);
    cudaGetSymbolAddress((void**)&B1,     g_B1);
    cudaGetSymbolAddress((void**)&B2,     g_B2);
    cudaGetSymbolAddress((void**)&Bf,     g_Bf);

    const int* src = idx;
    const int* dst = idx + E;

    // index normalize + CSR build
    detect_kernel<<<1, 256>>>((const int*)ei, E);
    convert_kernel<<<(2 * E + 255) / 256, 256>>>(ei, idx, 2 * E);
    cudaMemsetAsync(cnt, 0, (size_t)n * sizeof(int));
    deg_kernel<<<(E + 255) / 256, 256>>>(dst, cnt, E);
    scan_kernel<<<1, 1024>>>(cnt, off, cursor, n);
    scatter_kernel<<<(E + 255) / 256, 256>>>(src, dst, cursor, adj, E);

    // bake transposed hi/lo weight images
    wprep_kernel<<<(128 * 256 + 255) / 256, 256>>>(W1, B1, 256);
    wprep_kernel<<<(128 * 256 + 255) / 256, 256>>>(W2, B2, 256);
    {
        dim3 g(128, 3);
        wcombine_kernel<<<g, 128>>>(W0, Wp, WT, Wcat);
    }
    wprep_kernel<<<(128 * 384 + 255) / 256, 256>>>(Wcat, Bf, 384);

    const int gatherBlocks = (n + 7) / 8;
    const int gemmBlocks   = (n + 127) / 128;

    // layer 1
    gather_kernel<<<gatherBlocks, 256>>>(x, adj, off, cnt, agg, n);
    gemm_sage_mma<<<gemmBlocks, 256>>>(x, agg, B1, feat1, nullptr, n, n);

    // layer 2 (tail rows >= num stream into d_out)
    gather_kernel<<<gatherBlocks, 256>>>(feat1, adj, off, cnt, agg, n);
    gemm_sage_mma<<<gemmBlocks, 256>>>(feat1, agg, B2, feat2, out, n, num);

    // fused final
    gemm_final_mma<<<(num + 127) / 128, 256>>>(feat2, p0, p1, Bf, out, num);
}

// round 6
// speedup vs baseline: 2.0203x; 1.2765x over previous
#include <cuda_runtime.h>
#include <cuda_bf16.h>
#include <cstddef>
#include <cstdint>

// ---------------------------------------------------------------------------
// dygraphSAGE on GB300 (base sm_103 target): CSR-gather aggregation +
// mma.sync bf16 hi/lo GEMMs, temporal weights folded into one [384,128] GEMM
// ---------------------------------------------------------------------------

#define D128 128
#define MAXN 131072
#define MAXE 2097152
#define SCAN_CHUNK 1024
#define MAXBLKS (MAXN / SCAN_CHUNK)   // 128

// scratch (device globals -- allocation-free per harness rules)
__device__ float g_agg  [(size_t)MAXN * D128];
__device__ float g_feat1[(size_t)MAXN * D128];
__device__ float g_feat2[(size_t)MAXN * D128];
__device__ int   g_cnt[MAXN];
__device__ int   g_off[MAXN];
__device__ int   g_cursor[MAXN];
__device__ int   g_adj[MAXE];
__device__ int   g_blocksum[MAXBLKS];
__device__ int   g_blockbase[MAXBLKS];
__device__ float g_Wcat[384 * D128];
__device__ int   g_idx[2 * MAXE];
__device__ int   g_is64;
// pre-baked transposed weights Bt[n][k] bf16, hi image then lo image
__device__ __align__(16) uint16_t g_B1[2 * 128 * 256];
__device__ __align__(16) uint16_t g_B2[2 * 128 * 256];
__device__ __align__(16) uint16_t g_Bf[2 * 128 * 384];

// ---------------------------------------------------------------------------
// helpers
// ---------------------------------------------------------------------------
__device__ __forceinline__ void split2(float x0, float x1, uint32_t& hi, uint32_t& lo) {
    asm("cvt.rn.bf16x2.f32 %0, %1, %2;" : "=r"(hi) : "f"(x1), "f"(x0));
    float h0 = __uint_as_float(hi << 16);
    float h1 = __uint_as_float(hi & 0xffff0000u);
    asm("cvt.rn.bf16x2.f32 %0, %1, %2;" : "=r"(lo) : "f"(x1 - h1), "f"(x0 - h0));
}

__device__ __forceinline__ void mma16816(float* c, const uint32_t* a, const uint32_t* b) {
    asm volatile("mma.sync.aligned.m16n8k16.row.col.f32.bf16.bf16.f32 "
                 "{%0,%1,%2,%3}, {%4,%5,%6,%7}, {%8,%9}, {%0,%1,%2,%3};"
                 : "+f"(c[0]), "+f"(c[1]), "+f"(c[2]), "+f"(c[3])
                 : "r"(a[0]), "r"(a[1]), "r"(a[2]), "r"(a[3]),
                   "r"(b[0]), "r"(b[1]));
}

// ---------------------------------------------------------------------------
// index dtype sniff + normalize
// ---------------------------------------------------------------------------
__global__ void detect_kernel(const int* __restrict__ ei, int E) {
    __shared__ int any;
    if (threadIdx.x == 0) any = 0;
    __syncthreads();
    int cnt = E < 4096 ? E : 4096;
    for (int i = threadIdx.x; i < cnt; i += blockDim.x)
        if (ei[2 * i + 1] != 0) any = 1;
    __syncthreads();
    if (threadIdx.x == 0) g_is64 = any ? 0 : 1;
}

__global__ void convert_kernel(const void* __restrict__ ei, int* __restrict__ out, int total) {
    int i = blockIdx.x * blockDim.x + threadIdx.x;
    if (i >= total) return;
    if (g_is64) out[i] = (int)((const long long*)ei)[i];
    else        out[i] = ((const int*)ei)[i];
}

__global__ void deg_kernel(const int* __restrict__ dst, int* __restrict__ cnt, int E) {
    int e = blockIdx.x * blockDim.x + threadIdx.x;
    if (e < E) atomicAdd(&cnt[dst[e]], 1);
}

// ---------------------------------------------------------------------------
// 3-phase parallel exclusive scan of cnt -> off (+ cursor copy)
// ---------------------------------------------------------------------------
__global__ void scan_p1(const int* __restrict__ cnt, int* __restrict__ blocksum, int n) {
    __shared__ int red[1024];
    int b = blockIdx.x, t = threadIdx.x;
    int i = b * SCAN_CHUNK + t;
    red[t] = (i < n) ? cnt[i] : 0;
    __syncthreads();
    for (int d = 512; d > 0; d >>= 1) {
        if (t < d) red[t] += red[t + d];
        __syncthreads();
    }
    if (t == 0) blocksum[b] = red[0];
}

__global__ void scan_p2(const int* __restrict__ blocksum, int* __restrict__ blockbase, int B) {
    __shared__ int s[MAXBLKS];
    int t = threadIdx.x;
    s[t] = (t < B) ? blocksum[t] : 0;
    __syncthreads();
    for (int d = 1; d < MAXBLKS; d <<= 1) {
        int v = (t >= d) ? s[t - d] : 0;
        __syncthreads();
        s[t] += v;
        __syncthreads();
    }
    if (t < B) blockbase[t] = s[t] - blocksum[t];   // exclusive
}

__global__ void scan_p3(const int* __restrict__ cnt, const int* __restrict__ blockbase,
                        int* __restrict__ off, int* __restrict__ cursor, int n) {
    __shared__ int s[1024];
    int b = blockIdx.x, t = threadIdx.x;
    int i = b * SCAN_CHUNK + t;
    int v = (i < n) ? cnt[i] : 0;
    s[t] = v;
    __syncthreads();
    for (int d = 1; d < 1024; d <<= 1) {
        int u = (t >= d) ? s[t - d] : 0;
        __syncthreads();
        s[t] += u;
        __syncthreads();
    }
    if (i < n) {
        int e = blockbase[b] + s[t] - v;   // exclusive prefix
        off[i] = e;
        cursor[i] = e;
    }
}

__global__ void scatter_kernel(const int* __restrict__ src, const int* __restrict__ dst,
                               int* __restrict__ cursor, int* __restrict__ adj, int E) {
    int e = blockIdx.x * blockDim.x + threadIdx.x;
    if (e >= E) return;
    int pos = atomicAdd(&cursor[dst[e]], 1);
    adj[pos] = src[e];
}

// ---------------------------------------------------------------------------
// CSR gather mean-aggregation: one warp per node, lane owns 4 features.
// Writes agg already scaled by 1/max(deg,1).
// ---------------------------------------------------------------------------
__global__ __launch_bounds__(256)
void gather_kernel(const float* __restrict__ feat, const int* __restrict__ adj,
                   const int* __restrict__ off, const int* __restrict__ cnt,
                   float* __restrict__ agg, int n) {
    int w    = (int)((blockIdx.x * (size_t)blockDim.x + threadIdx.x) >> 5);
    int lane = threadIdx.x & 31;
    if (w >= n) return;
    const int start = off[w];
    const int deg   = cnt[w];
    float ax = 0.f, ay = 0.f, az = 0.f, aw = 0.f;
    int i = 0;
    for (; i + 4 <= deg; i += 4) {
        int s0 = adj[start + i + 0];
        int s1 = adj[start + i + 1];
        int s2 = adj[start + i + 2];
        int s3 = adj[start + i + 3];
        float4 v0 = *(const float4*)&feat[(size_t)s0 * D128 + lane * 4];
        float4 v1 = *(const float4*)&feat[(size_t)s1 * D128 + lane * 4];
        float4 v2 = *(const float4*)&feat[(size_t)s2 * D128 + lane * 4];
        float4 v3 = *(const float4*)&feat[(size_t)s3 * D128 + lane * 4];
        ax += (v0.x + v1.x) + (v2.x + v3.x);
        ay += (v0.y + v1.y) + (v2.y + v3.y);
        az += (v0.z + v1.z) + (v2.z + v3.z);
        aw += (v0.w + v1.w) + (v2.w + v3.w);
    }
    for (; i < deg; i++) {
        int s = adj[start + i];
        float4 v = *(const float4*)&feat[(size_t)s * D128 + lane * 4];
        ax += v.x; ay += v.y; az += v.z; aw += v.w;
    }
    float sc = 1.0f / (float)(deg > 1 ? deg : 1);
    float4 o = make_float4(ax * sc, ay * sc, az * sc, aw * sc);
    *(float4*)&agg[(size_t)w * D128 + lane * 4] = o;
}

// ---------------------------------------------------------------------------
// temporal weight fold (Wcat [384,128] fp32)
// ---------------------------------------------------------------------------
__global__ void wcombine_kernel(const float* __restrict__ W0,
                                const float* __restrict__ Wp,
                                const float* __restrict__ WT,
                                float* __restrict__ Wcat) {
    int row = blockIdx.x;
    int m   = blockIdx.y;
    int col = threadIdx.x;
    __shared__ float L[128];
    const float* Lsrc = (m == 0) ? W0 : (Wp + (size_t)(m - 1) * 128 * 128);
    L[col] = Lsrc[row * 128 + col];
    __syncthreads();
    float s = 0.f;
#pragma unroll 8
    for (int k = 0; k < 128; k++)
        s = fmaf(L[k], WT[(size_t)(128 + k) * 128 + col], s);
    s *= (1.0f / 3.0f);
    if (m == 0) s += WT[(size_t)row * 128 + col];
    Wcat[(size_t)(m * 128 + row) * 128 + col] = s;
}

// ---------------------------------------------------------------------------
// bake W [K,128] fp32 -> Bt[n][k] bf16 (hi image at 0, lo image at 128*K)
// ---------------------------------------------------------------------------
__global__ void wprep_kernel(const float* __restrict__ W, uint16_t* __restrict__ img, int K) {
    int idx = blockIdx.x * blockDim.x + threadIdx.x;
    if (idx >= 128 * K) return;
    int nn = idx / K, k = idx % K;
    float x = W[(size_t)k * 128 + nn];
    __nv_bfloat16 h = __float2bfloat16_rn(x);
    float hf = __bfloat162float(h);
    __nv_bfloat16 l = __float2bfloat16_rn(x - hf);
    img[(size_t)nn * K + k]                    = *(uint16_t*)&h;
    img[(size_t)128 * K + (size_t)nn * K + k]  = *(uint16_t*)&l;
}

// ---------------------------------------------------------------------------
// SAGE layer GEMM (tensor): OUT = relu([H | AGG] @ W), K=256, AGG pre-scaled
// ---------------------------------------------------------------------------
__global__ __launch_bounds__(256, 1)
void gemm_sage_mma(const float* __restrict__ H, const float* __restrict__ AGG,
                   const uint16_t* __restrict__ Bt,
                   float* __restrict__ OUT, float* __restrict__ tail,
                   int n, int numTail) {
    __shared__ __align__(16) uint16_t As_hi[2][128][16];
    __shared__ __align__(16) uint16_t As_lo[2][128][16];
    __shared__ __align__(16) uint16_t Bs_hi[2][128][16];
    __shared__ __align__(16) uint16_t Bs_lo[2][128][16];

    const int K = 256;
    const int tid  = threadIdx.x;
    const int lane = tid & 31;
    const int wid  = tid >> 5;
    const int wm   = wid & 3;
    const int wn   = wid >> 2;
    const int rowBase = blockIdx.x * 128;

    const int arow = tid >> 1;
    const int koff = (tid & 1) * 8;
    const int grow = rowBase + arow;
    const bool rv  = grow < n;
    const float* hptr = H   + (size_t)(rv ? grow : 0) * D128;
    const float* aptr = AGG + (size_t)(rv ? grow : 0) * D128;
    const size_t bbase = (size_t)arow * K;

    float acc[2][8][4];
#pragma unroll
    for (int mt = 0; mt < 2; mt++)
#pragma unroll
        for (int nt = 0; nt < 8; nt++)
#pragma unroll
            for (int q = 0; q < 4; q++) acc[mt][nt][q] = 0.f;

    float4 pa, pb;
    uint4  pbh, pbl;
    {
        pa = rv ? *(const float4*)&hptr[koff]     : make_float4(0, 0, 0, 0);
        pb = rv ? *(const float4*)&hptr[koff + 4] : make_float4(0, 0, 0, 0);
        pbh = *(const uint4*)&Bt[bbase + koff];
        pbl = *(const uint4*)&Bt[(size_t)128 * K + bbase + koff];
    }

    int stage = 0;
    const int NK = K / 16;
#pragma unroll 1
    for (int ks = 0; ks < NK; ks++) {
        {
            uint32_t h0, l0, h1, l1, h2, l2, h3, l3;
            split2(pa.x, pa.y, h0, l0);
            split2(pa.z, pa.w, h1, l1);
            split2(pb.x, pb.y, h2, l2);
            split2(pb.z, pb.w, h3, l3);
            *(uint4*)&As_hi[stage][arow][koff] = make_uint4(h0, h1, h2, h3);
            *(uint4*)&As_lo[stage][arow][koff] = make_uint4(l0, l1, l2, l3);
            *(uint4*)&Bs_hi[stage][arow][koff] = pbh;
            *(uint4*)&Bs_lo[stage][arow][koff] = pbl;
        }
        __syncthreads();
        if (ks + 1 < NK) {
            int kb = (ks + 1) * 16;
            if (rv) {
                const float* s = (kb < 128) ? (hptr + kb) : (aptr + kb - 128);
                pa = *(const float4*)&s[koff];
                pb = *(const float4*)&s[koff + 4];
            }
            pbh = *(const uint4*)&Bt[bbase + kb + koff];
            pbl = *(const uint4*)&Bt[(size_t)128 * K + bbase + kb + koff];
        }
        {
            const int r  = lane >> 2;
            const int c2 = (lane & 3) * 2;
            uint32_t bh[8][2], bl[8][2];
#pragma unroll
            for (int nt = 0; nt < 8; nt++) {
                int nn = wn * 64 + nt * 8 + r;
                bh[nt][0] = *(const uint32_t*)&Bs_hi[stage][nn][c2];
                bh[nt][1] = *(const uint32_t*)&Bs_hi[stage][nn][c2 + 8];
                bl[nt][0] = *(const uint32_t*)&Bs_lo[stage][nn][c2];
                bl[nt][1] = *(const uint32_t*)&Bs_lo[stage][nn][c2 + 8];
            }
#pragma unroll
            for (int mt = 0; mt < 2; mt++) {
                int r0 = wm * 32 + mt * 16;
                uint32_t ah[4], al[4];
                ah[0] = *(const uint32_t*)&As_hi[stage][r0 + r][c2];
                ah[1] = *(const uint32_t*)&As_hi[stage][r0 + r + 8][c2];
                ah[2] = *(const uint32_t*)&As_hi[stage][r0 + r][c2 + 8];
                ah[3] = *(const uint32_t*)&As_hi[stage][r0 + r + 8][c2 + 8];
                al[0] = *(const uint32_t*)&As_lo[stage][r0 + r][c2];
                al[1] = *(const uint32_t*)&As_lo[stage][r0 + r + 8][c2];
                al[2] = *(const uint32_t*)&As_lo[stage][r0 + r][c2 + 8];
                al[3] = *(const uint32_t*)&As_lo[stage][r0 + r + 8][c2 + 8];
#pragma unroll
                for (int nt = 0; nt < 8; nt++) {
                    mma16816(acc[mt][nt], ah, bh[nt]);
                    mma16816(acc[mt][nt], ah, bl[nt]);
                    mma16816(acc[mt][nt], al, bh[nt]);
                }
            }
        }
        stage ^= 1;
    }

    const int r  = lane >> 2;
    const int c2 = (lane & 3) * 2;
#pragma unroll
    for (int mt = 0; mt < 2; mt++) {
#pragma unroll
        for (int half = 0; half < 2; half++) {
            int row = rowBase + wm * 32 + mt * 16 + half * 8 + r;
            if (row >= n) continue;
#pragma unroll
            for (int nt = 0; nt < 8; nt++) {
                int col = wn * 64 + nt * 8 + c2;
                float2 o;
                o.x = fmaxf(acc[mt][nt][half * 2 + 0], 0.f);
                o.y = fmaxf(acc[mt][nt][half * 2 + 1], 0.f);
                *(float2*)&OUT[(size_t)row * D128 + col] = o;
                if (tail != nullptr && row >= numTail)
                    *(float2*)&tail[(size_t)row * D128 + col] = o;
            }
        }
    }
}

// ---------------------------------------------------------------------------
// final fused GEMM (tensor): f = leakyrelu([F2|P0|P1] @ Wcat, 0.2)
//                            out = f / max(||f||, 1e-12) ;  K = 384
// ---------------------------------------------------------------------------
__global__ __launch_bounds__(256, 1)
void gemm_final_mma(const float* __restrict__ F2, const float* __restrict__ P0,
                    const float* __restrict__ P1, const uint16_t* __restrict__ Bt,
                    float* __restrict__ OUT, int num) {
    __shared__ __align__(16) uint16_t As_hi[2][128][16];
    __shared__ __align__(16) uint16_t As_lo[2][128][16];
    __shared__ __align__(16) uint16_t Bs_hi[2][128][16];
    __shared__ __align__(16) uint16_t Bs_lo[2][128][16];
    __shared__ float ssbuf[2][128];

    const int K = 384;
    const int tid  = threadIdx.x;
    const int lane = tid & 31;
    const int wid  = tid >> 5;
    const int wm   = wid & 3;
    const int wn   = wid >> 2;
    const int rowBase = blockIdx.x * 128;

    const int arow = tid >> 1;
    const int koff = (tid & 1) * 8;
    const int grow = rowBase + arow;
    const bool rv  = grow < num;
    const size_t ro = (size_t)(rv ? grow : 0) * D128;
    const size_t bbase = (size_t)arow * K;

    float acc[2][8][4];
#pragma unroll
    for (int mt = 0; mt < 2; mt++)
#pragma unroll
        for (int nt = 0; nt < 8; nt++)
#pragma unroll
            for (int q = 0; q < 4; q++) acc[mt][nt][q] = 0.f;

    float4 pa, pb;
    uint4  pbh, pbl;
    {
        pa = rv ? *(const float4*)&F2[ro + koff]     : make_float4(0, 0, 0, 0);
        pb = rv ? *(const float4*)&F2[ro + koff + 4] : make_float4(0, 0, 0, 0);
        pbh = *(const uint4*)&Bt[bbase + koff];
        pbl = *(const uint4*)&Bt[(size_t)128 * K + bbase + koff];
    }

    int stage = 0;
    const int NK = K / 16;
#pragma unroll 1
    for (int ks = 0; ks < NK; ks++) {
        {
            uint32_t h0, l0, h1, l1, h2, l2, h3, l3;
            split2(pa.x, pa.y, h0, l0);
            split2(pa.z, pa.w, h1, l1);
            split2(pb.x, pb.y, h2, l2);
            split2(pb.z, pb.w, h3, l3);
            *(uint4*)&As_hi[stage][arow][koff] = make_uint4(h0, h1, h2, h3);
            *(uint4*)&As_lo[stage][arow][koff] = make_uint4(l0, l1, l2, l3);
            *(uint4*)&Bs_hi[stage][arow][koff] = pbh;
            *(uint4*)&Bs_lo[stage][arow][koff] = pbl;
        }
        __syncthreads();
        if (ks + 1 < NK) {
            int kb = (ks + 1) * 16;
            if (rv) {
                const float* s = (kb < 128) ? (F2 + ro + kb)
                               : (kb < 256) ? (P0 + ro + kb - 128)
                                            : (P1 + ro + kb - 256);
                pa = *(const float4*)&s[koff];
                pb = *(const float4*)&s[koff + 4];
            }
            pbh = *(const uint4*)&Bt[bbase + kb + koff];
            pbl = *(const uint4*)&Bt[(size_t)128 * K + bbase + kb + koff];
        }
        {
            const int r  = lane >> 2;
            const int c2 = (lane & 3) * 2;
            uint32_t bh[8][2], bl[8][2];
#pragma unroll
            for (int nt = 0; nt < 8; nt++) {
                int nn = wn * 64 + nt * 8 + r;
                bh[nt][0] = *(const uint32_t*)&Bs_hi[stage][nn][c2];
                bh[nt][1] = *(const uint32_t*)&Bs_hi[stage][nn][c2 + 8];
                bl[nt][0] = *(const uint32_t*)&Bs_lo[stage][nn][c2];
                bl[nt][1] = *(const uint32_t*)&Bs_lo[stage][nn][c2 + 8];
            }
#pragma unroll
            for (int mt = 0; mt < 2; mt++) {
                int r0 = wm * 32 + mt * 16;
                uint32_t ah[4], al[4];
                ah[0] = *(const uint32_t*)&As_hi[stage][r0 + r][c2];
                ah[1] = *(const uint32_t*)&As_hi[stage][r0 + r + 8][c2];
                ah[2] = *(const uint32_t*)&As_hi[stage][r0 + r][c2 + 8];
                ah[3] = *(const uint32_t*)&As_hi[stage][r0 + r + 8][c2 + 8];
                al[0] = *(const uint32_t*)&As_lo[stage][r0 + r][c2];
                al[1] = *(const uint32_t*)&As_lo[stage][r0 + r + 8][c2];
                al[2] = *(const uint32_t*)&As_lo[stage][r0 + r][c2 + 8];
                al[3] = *(const uint32_t*)&As_lo[stage][r0 + r + 8][c2 + 8];
#pragma unroll
                for (int nt = 0; nt < 8; nt++) {
                    mma16816(acc[mt][nt], ah, bh[nt]);
                    mma16816(acc[mt][nt], ah, bl[nt]);
                    mma16816(acc[mt][nt], al, bh[nt]);
                }
            }
        }
        stage ^= 1;
    }

    const int r  = lane >> 2;
    float ss[2][2] = {{0.f, 0.f}, {0.f, 0.f}};
#pragma unroll
    for (int mt = 0; mt < 2; mt++)
#pragma unroll
        for (int nt = 0; nt < 8; nt++)
#pragma unroll
            for (int q = 0; q < 4; q++) {
                float v = acc[mt][nt][q];
                v = (v > 0.f) ? v : 0.2f * v;
                acc[mt][nt][q] = v;
                ss[mt][q >> 1] = fmaf(v, v, ss[mt][q >> 1]);
            }
#pragma unroll
    for (int m = 1; m < 4; m <<= 1) {
#pragma unroll
        for (int mt = 0; mt < 2; mt++) {
            ss[mt][0] += __shfl_xor_sync(0xffffffffu, ss[mt][0], m);
            ss[mt][1] += __shfl_xor_sync(0xffffffffu, ss[mt][1], m);
        }
    }
    if ((lane & 3) == 0) {
#pragma unroll
        for (int mt = 0; mt < 2; mt++)
#pragma unroll
            for (int half = 0; half < 2; half++)
                ssbuf[wn][wm * 32 + mt * 16 + half * 8 + r] = ss[mt][half];
    }
    __syncthreads();

    const int c2 = (lane & 3) * 2;
#pragma unroll
    for (int mt = 0; mt < 2; mt++) {
#pragma unroll
        for (int half = 0; half < 2; half++) {
            int rl  = wm * 32 + mt * 16 + half * 8 + r;
            int row = rowBase + rl;
            if (row >= num) continue;
            float tot = ssbuf[0][rl] + ssbuf[1][rl];
            float inv = 1.0f / fmaxf(sqrtf(tot), 1e-12f);
#pragma unroll
            for (int nt = 0; nt < 8; nt++) {
                int col = wn * 64 + nt * 8 + c2;
                float2 o;
                o.x = acc[mt][nt][half * 2 + 0] * inv;
                o.y = acc[mt][nt][half * 2 + 1] * inv;
                *(float2*)&OUT[(size_t)row * D128 + col] = o;
            }
        }
    }
}

// ---------------------------------------------------------------------------
// launch
// ---------------------------------------------------------------------------
extern "C" void kernel_launch(void* const* d_in, const int* in_sizes, int n_in,
                              void* d_out, int out_size) {
    const float* x    = (const float*)d_in[0];
    const float* past = (const float*)d_in[1];
    const float* W1   = (const float*)d_in[2];
    const float* W2   = (const float*)d_in[3];
    const float* W0   = (const float*)d_in[4];
    const float* Wp   = (const float*)d_in[5];
    const float* WT   = (const float*)d_in[6];
    const void*  ei   = d_in[7];
    float*       out  = (float*)d_out;

    const int n   = in_sizes[0] / D128;
    const int num = in_sizes[1] / (2 * D128);
    const int E   = in_sizes[7] / 2;

    const float* p0 = past;
    const float* p1 = past + (size_t)num * D128;

    float *agg, *feat1, *feat2, *Wcat;
    int *cnt, *off, *cursor, *adj, *idx, *bsum, *bbase;
    uint16_t *B1, *B2, *Bf;
    cudaGetSymbolAddress((void**)&agg,    g_agg);
    cudaGetSymbolAddress((void**)&feat1,  g_feat1);
    cudaGetSymbolAddress((void**)&feat2,  g_feat2);
    cudaGetSymbolAddress((void**)&cnt,    g_cnt);
    cudaGetSymbolAddress((void**)&off,    g_off);
    cudaGetSymbolAddress((void**)&cursor, g_cursor);
    cudaGetSymbolAddress((void**)&adj,    g_adj);
    cudaGetSymbolAddress((void**)&bsum,   g_blocksum);
    cudaGetSymbolAddress((void**)&bbase,  g_blockbase);
    cudaGetSymbolAddress((void**)&Wcat,   g_Wcat);
    cudaGetSymbolAddress((void**)&idx,    g_idx);
    cudaGetSymbolAddress((void**)&B1,     g_B1);
    cudaGetSymbolAddress((void**)&B2,     g_B2);
    cudaGetSymbolAddress((void**)&Bf,     g_Bf);

    const int* src = idx;
    const int* dst = idx + E;

    // index normalize + CSR build
    detect_kernel<<<1, 256>>>((const int*)ei, E);
    convert_kernel<<<(2 * E + 255) / 256, 256>>>(ei, idx, 2 * E);
    cudaMemsetAsync(cnt, 0, (size_t)n * sizeof(int));
    deg_kernel<<<(E + 255) / 256, 256>>>(dst, cnt, E);
    const int scanBlocks = (n + SCAN_CHUNK - 1) / SCAN_CHUNK;
    scan_p1<<<scanBlocks, 1024>>>(cnt, bsum, n);
    scan_p2<<<1, MAXBLKS>>>(bsum, bbase, scanBlocks);
    scan_p3<<<scanBlocks, 1024>>>(cnt, bbase, off, cursor, n);
    scatter_kernel<<<(E + 255) / 256, 256>>>(src, dst, cursor, adj, E);

    // bake transposed hi/lo weight images
    wprep_kernel<<<(128 * 256 + 255) / 256, 256>>>(W1, B1, 256);
    wprep_kernel<<<(128 * 256 + 255) / 256, 256>>>(W2, B2, 256);
    {
        dim3 g(128, 3);
        wcombine_kernel<<<g, 128>>>(W0, Wp, WT, Wcat);
    }
    wprep_kernel<<<(128 * 384 + 255) / 256, 256>>>(Wcat, Bf, 384);

    const int gatherBlocks = (n + 7) / 8;
    const int gemmBlocks   = (n + 127) / 128;

    // layer 1
    gather_kernel<<<gatherBlocks, 256>>>(x, adj, off, cnt, agg, n);
    gemm_sage_mma<<<gemmBlocks, 256>>>(x, agg, B1, feat1, nullptr, n, n);

    // layer 2 (tail rows >= num stream into d_out)
    gather_kernel<<<gatherBlocks, 256>>>(feat1, adj, off, cnt, agg, n);
    gemm_sage_mma<<<gemmBlocks, 256>>>(feat1, agg, B2, feat2, out, n, num);

    // fused final
    gemm_final_mma<<<(num + 127) / 128, 256>>>(feat2, p0, p1, Bf, out, num);
}

// round 7
// speedup vs baseline: 2.3826x; 1.1793x over previous
#include <cuda_runtime.h>
#include <cuda_bf16.h>
#include <cstddef>
#include <cstdint>

// ---------------------------------------------------------------------------
// dygraphSAGE on GB300 (base sm_103 target): CSR-gather aggregation +
// mma.sync bf16 hi/lo GEMMs (fragment-baked B, conflict-free smem)
// ---------------------------------------------------------------------------

#define D128 128
#define MAXN 131072
#define MAXE 2097152
#define SCAN_CHUNK 1024
#define MAXBLKS (MAXN / SCAN_CHUNK)   // 128

// scratch (device globals -- allocation-free per harness rules)
__device__ float g_agg  [(size_t)MAXN * D128];
__device__ float g_feat1[(size_t)MAXN * D128];
__device__ float g_feat2[(size_t)MAXN * D128];
__device__ int   g_cnt[MAXN];
__device__ int   g_off[MAXN];
__device__ int   g_cursor[MAXN];
__device__ int   g_adj[MAXE];
__device__ int   g_blocksum[MAXBLKS];
__device__ float g_Wcat[384 * D128];
__device__ int   g_is64;
// fragment-order baked weights: per plane (hi, lo): word idx
// ((ks*128 + nn)*4 + tig)*2 + w   (uint32 words, 2 bf16 each)
__device__ __align__(16) uint16_t g_B1[2 * 128 * 256];
__device__ __align__(16) uint16_t g_B2[2 * 128 * 256];
__device__ __align__(16) uint16_t g_Bf[2 * 128 * 384];

// ---------------------------------------------------------------------------
// helpers
// ---------------------------------------------------------------------------
__device__ __forceinline__ void split2(float x0, float x1, uint32_t& hi, uint32_t& lo) {
    asm("cvt.rn.bf16x2.f32 %0, %1, %2;" : "=r"(hi) : "f"(x1), "f"(x0));
    float h0 = __uint_as_float(hi << 16);
    float h1 = __uint_as_float(hi & 0xffff0000u);
    asm("cvt.rn.bf16x2.f32 %0, %1, %2;" : "=r"(lo) : "f"(x1 - h1), "f"(x0 - h0));
}

__device__ __forceinline__ void mma16816(float* c, const uint32_t* a, const uint32_t* b) {
    asm volatile("mma.sync.aligned.m16n8k16.row.col.f32.bf16.bf16.f32 "
                 "{%0,%1,%2,%3}, {%4,%5,%6,%7}, {%8,%9}, {%0,%1,%2,%3};"
                 : "+f"(c[0]), "+f"(c[1]), "+f"(c[2]), "+f"(c[3])
                 : "r"(a[0]), "r"(a[1]), "r"(a[2]), "r"(a[3]),
                   "r"(b[0]), "r"(b[1]));
}

// ---------------------------------------------------------------------------
// zero cnt + detect index dtype (block 0 samples)
// ---------------------------------------------------------------------------
__global__ void zdetect_kernel(const int* __restrict__ ei, int* __restrict__ cnt,
                               int E, int n) {
    int i = blockIdx.x * blockDim.x + threadIdx.x;
    if (i < n) cnt[i] = 0;
    if (blockIdx.x == 0) {
        __shared__ int any;
        if (threadIdx.x == 0) any = 0;
        __syncthreads();
        int c = E < 4096 ? E : 4096;
        for (int j = threadIdx.x; j < c; j += blockDim.x)
            if (ei[2 * j + 1] != 0) any = 1;
        __syncthreads();
        if (threadIdx.x == 0) g_is64 = any ? 0 : 1;
    }
}

__device__ __forceinline__ int load_idx(const void* ei, size_t pos) {
    return g_is64 ? (int)((const long long*)ei)[pos] : ((const int*)ei)[pos];
}

__global__ void deg_kernel(const void* __restrict__ ei, int* __restrict__ cnt, int E) {
    int e = blockIdx.x * blockDim.x + threadIdx.x;
    if (e < E) atomicAdd(&cnt[load_idx(ei, (size_t)E + e)], 1);
}

// ---------------------------------------------------------------------------
// 2-phase parallel exclusive scan of cnt -> off (+ cursor copy)
// ---------------------------------------------------------------------------
__global__ void scan_p1(const int* __restrict__ cnt, int* __restrict__ blocksum, int n) {
    __shared__ int red[1024];
    int b = blockIdx.x, t = threadIdx.x;
    int i = b * SCAN_CHUNK + t;
    red[t] = (i < n) ? cnt[i] : 0;
    __syncthreads();
    for (int d = 512; d > 0; d >>= 1) {
        if (t < d) red[t] += red[t + d];
        __syncthreads();
    }
    if (t == 0) blocksum[b] = red[0];
}

__global__ void scan_p3(const int* __restrict__ cnt, const int* __restrict__ blocksum,
                        int* __restrict__ off, int* __restrict__ cursor, int n, int B) {
    __shared__ int s[1024];
    __shared__ int bs[MAXBLKS];
    int b = blockIdx.x, t = threadIdx.x;
    if (t < MAXBLKS) bs[t] = (t < B) ? blocksum[t] : 0;
    __syncthreads();
    for (int d = 1; d < MAXBLKS; d <<= 1) {
        int v = 0;
        if (t < MAXBLKS && t >= d) v = bs[t - d];
        __syncthreads();
        if (t < MAXBLKS) bs[t] += v;
        __syncthreads();
    }
    int base = (b == 0) ? 0 : bs[b - 1];
    int i = b * SCAN_CHUNK + t;
    int v = (i < n) ? cnt[i] : 0;
    s[t] = v;
    __syncthreads();
    for (int d = 1; d < 1024; d <<= 1) {
        int u = (t >= d) ? s[t - d] : 0;
        __syncthreads();
        s[t] += u;
        __syncthreads();
    }
    if (i < n) {
        int e = base + s[t] - v;
        off[i] = e;
        cursor[i] = e;
    }
}

__global__ void scatter_kernel(const void* __restrict__ ei,
                               int* __restrict__ cursor, int* __restrict__ adj, int E) {
    int e = blockIdx.x * blockDim.x + threadIdx.x;
    if (e >= E) return;
    int d = load_idx(ei, (size_t)E + e);
    int s = load_idx(ei, e);
    int pos = atomicAdd(&cursor[d], 1);
    adj[pos] = s;
}

// ---------------------------------------------------------------------------
// CSR gather mean-aggregation: one warp per node, lane owns 4 features.
// Writes agg already scaled by 1/max(deg,1).
// ---------------------------------------------------------------------------
__global__ __launch_bounds__(256)
void gather_kernel(const float* __restrict__ feat, const int* __restrict__ adj,
                   const int* __restrict__ off, const int* __restrict__ cnt,
                   float* __restrict__ agg, int n) {
    int w    = (int)((blockIdx.x * (size_t)blockDim.x + threadIdx.x) >> 5);
    int lane = threadIdx.x & 31;
    if (w >= n) return;
    const int start = off[w];
    const int deg   = cnt[w];
    float ax = 0.f, ay = 0.f, az = 0.f, aw = 0.f;
    int i = 0;
    for (; i + 4 <= deg; i += 4) {
        int s0 = adj[start + i + 0];
        int s1 = adj[start + i + 1];
        int s2 = adj[start + i + 2];
        int s3 = adj[start + i + 3];
        float4 v0 = *(const float4*)&feat[(size_t)s0 * D128 + lane * 4];
        float4 v1 = *(const float4*)&feat[(size_t)s1 * D128 + lane * 4];
        float4 v2 = *(const float4*)&feat[(size_t)s2 * D128 + lane * 4];
        float4 v3 = *(const float4*)&feat[(size_t)s3 * D128 + lane * 4];
        ax += (v0.x + v1.x) + (v2.x + v3.x);
        ay += (v0.y + v1.y) + (v2.y + v3.y);
        az += (v0.z + v1.z) + (v2.z + v3.z);
        aw += (v0.w + v1.w) + (v2.w + v3.w);
    }
    for (; i < deg; i++) {
        int s = adj[start + i];
        float4 v = *(const float4*)&feat[(size_t)s * D128 + lane * 4];
        ax += v.x; ay += v.y; az += v.z; aw += v.w;
    }
    float sc = 1.0f / (float)(deg > 1 ? deg : 1);
    float4 o = make_float4(ax * sc, ay * sc, az * sc, aw * sc);
    *(float4*)&agg[(size_t)w * D128 + lane * 4] = o;
}

// ---------------------------------------------------------------------------
// temporal weight fold (Wcat [384,128] fp32)
// ---------------------------------------------------------------------------
__global__ void wcombine_kernel(const float* __restrict__ W0,
                                const float* __restrict__ Wp,
                                const float* __restrict__ WT,
                                float* __restrict__ Wcat) {
    int row = blockIdx.x;
    int m   = blockIdx.y;
    int col = threadIdx.x;
    __shared__ float L[128];
    const float* Lsrc = (m == 0) ? W0 : (Wp + (size_t)(m - 1) * 128 * 128);
    L[col] = Lsrc[row * 128 + col];
    __syncthreads();
    float s = 0.f;
#pragma unroll 8
    for (int k = 0; k < 128; k++)
        s = fmaf(L[k], WT[(size_t)(128 + k) * 128 + col], s);
    s *= (1.0f / 3.0f);
    if (m == 0) s += WT[(size_t)row * 128 + col];
    Wcat[(size_t)(m * 128 + row) * 128 + col] = s;
}

// ---------------------------------------------------------------------------
// bake W [K,128] fp32 -> fragment-order bf16 planes (hi at 0, lo at 128*K u16)
// word idx ((ks*128+nn)*4 + tig)*2 + w ; halves: kin&1
// ---------------------------------------------------------------------------
__global__ void wprep_kernel(const float* __restrict__ W, uint16_t* __restrict__ img, int K) {
    int idx = blockIdx.x * blockDim.x + threadIdx.x;
    if (idx >= 128 * K) return;
    int nn = idx / K, k = idx % K;
    float x = W[(size_t)k * 128 + nn];
    __nv_bfloat16 h = __float2bfloat16_rn(x);
    float hf = __bfloat162float(h);
    __nv_bfloat16 l = __float2bfloat16_rn(x - hf);
    int ks = k >> 4, kin = k & 15;
    int tig = (kin >> 1) & 3, w = kin >> 3, half = kin & 1;
    size_t u16pos = (size_t)((((ks * 128 + nn) * 4 + tig) * 2 + w) * 2 + half);
    img[u16pos]                     = *(uint16_t*)&h;
    img[(size_t)128 * K + u16pos]   = *(uint16_t*)&l;
}

// ---------------------------------------------------------------------------
// GEMM smem layout constants (dynamic smem, 56KB):
//  as_hi: words [0, 2*2560)      (stage-major, row stride 20 words, 80B)
//  as_lo: words [5120, 10240)
//  bs_hi: words [10240, 12288)   (stage-major, 1024 words/stage)
//  bs_lo: words [12288, 14336)
// ---------------------------------------------------------------------------
#define AS_STRIDE 20
#define AS_WORDS  (128 * AS_STRIDE)      // 2560
#define BS_WORDS  1024
#define SM_ASHI   0
#define SM_ASLO   (2 * AS_WORDS)
#define SM_BSHI   (4 * AS_WORDS)
#define SM_BSLO   (4 * AS_WORDS + 2 * BS_WORDS)
#define SM_TOTAL_BYTES ((4 * AS_WORDS + 4 * BS_WORDS) * 4)   // 57344

// ---------------------------------------------------------------------------
// SAGE layer GEMM: OUT = relu([H | AGG] @ W), K=256, AGG pre-scaled
// ---------------------------------------------------------------------------
__global__ __launch_bounds__(256, 1)
void gemm_sage_mma(const float* __restrict__ H, const float* __restrict__ AGG,
                   const uint32_t* __restrict__ Bt,
                   float* __restrict__ OUT, float* __restrict__ tail,
                   int n, int numTail) {
    extern __shared__ uint32_t sm[];
    uint32_t* as_hi = sm + SM_ASHI;
    uint32_t* as_lo = sm + SM_ASLO;
    uint32_t* bs_hi = sm + SM_BSHI;
    uint32_t* bs_lo = sm + SM_BSLO;

    const int K = 256;
    const int KW = K * 64;               // words per B plane
    const int tid  = threadIdx.x;
    const int lane = tid & 31;
    const int wid  = tid >> 5;
    const int wm   = wid & 3;
    const int wn   = wid >> 2;
    const int rowBase = blockIdx.x * 128;

    const int arow = tid >> 1;
    const int ahalf = tid & 1;           // k offset = ahalf*8 elements
    const int grow = rowBase + arow;
    const bool rv  = grow < n;
    const float* hptr = H   + (size_t)(rv ? grow : 0) * D128;
    const float* aptr = AGG + (size_t)(rv ? grow : 0) * D128;

    float acc[2][8][4];
#pragma unroll
    for (int mt = 0; mt < 2; mt++)
#pragma unroll
        for (int nt = 0; nt < 8; nt++)
#pragma unroll
            for (int q = 0; q < 4; q++) acc[mt][nt][q] = 0.f;

    float4 pa, pb;
    uint4  pbh, pbl;
    {
        pa = rv ? *(const float4*)&hptr[ahalf * 8]     : make_float4(0, 0, 0, 0);
        pb = rv ? *(const float4*)&hptr[ahalf * 8 + 4] : make_float4(0, 0, 0, 0);
        pbh = *(const uint4*)&Bt[tid * 4];
        pbl = *(const uint4*)&Bt[KW + tid * 4];
    }

    int stage = 0;
    const int NK = K / 16;
#pragma unroll 1
    for (int ks = 0; ks < NK; ks++) {
        {
            uint32_t h0, l0, h1, l1, h2, l2, h3, l3;
            split2(pa.x, pa.y, h0, l0);
            split2(pa.z, pa.w, h1, l1);
            split2(pb.x, pb.y, h2, l2);
            split2(pb.z, pb.w, h3, l3);
            int aw = stage * AS_WORDS + arow * AS_STRIDE + ahalf * 4;
            *(uint4*)&as_hi[aw] = make_uint4(h0, h1, h2, h3);
            *(uint4*)&as_lo[aw] = make_uint4(l0, l1, l2, l3);
            int bw = stage * BS_WORDS + tid * 4;
            *(uint4*)&bs_hi[bw] = pbh;
            *(uint4*)&bs_lo[bw] = pbl;
        }
        __syncthreads();
        if (ks + 1 < NK) {
            int kb = (ks + 1) * 16;
            if (rv) {
                const float* s = (kb < 128) ? (hptr + kb) : (aptr + kb - 128);
                pa = *(const float4*)&s[ahalf * 8];
                pb = *(const float4*)&s[ahalf * 8 + 4];
            }
            pbh = *(const uint4*)&Bt[(ks + 1) * BS_WORDS + tid * 4];
            pbl = *(const uint4*)&Bt[KW + (ks + 1) * BS_WORDS + tid * 4];
        }
        {
            const int r = lane >> 2;
            const int p = lane & 3;
            uint32_t bh[8][2], bl[8][2];
#pragma unroll
            for (int nt = 0; nt < 8; nt++) {
                int nn = wn * 64 + nt * 8 + r;
                uint2 th = *(const uint2*)&bs_hi[stage * BS_WORDS + (nn * 4 + p) * 2];
                uint2 tl = *(const uint2*)&bs_lo[stage * BS_WORDS + (nn * 4 + p) * 2];
                bh[nt][0] = th.x; bh[nt][1] = th.y;
                bl[nt][0] = tl.x; bl[nt][1] = tl.y;
            }
#pragma unroll
            for (int mt = 0; mt < 2; mt++) {
                int r0 = wm * 32 + mt * 16;
                int ab = stage * AS_WORDS + (r0 + r) * AS_STRIDE + p;
                uint32_t ah[4], al[4];
                ah[0] = as_hi[ab];
                ah[1] = as_hi[ab + 8 * AS_STRIDE];
                ah[2] = as_hi[ab + 4];
                ah[3] = as_hi[ab + 8 * AS_STRIDE + 4];
                al[0] = as_lo[ab];
                al[1] = as_lo[ab + 8 * AS_STRIDE];
                al[2] = as_lo[ab + 4];
                al[3] = as_lo[ab + 8 * AS_STRIDE + 4];
#pragma unroll
                for (int nt = 0; nt < 8; nt++) {
                    mma16816(acc[mt][nt], ah, bh[nt]);
                    mma16816(acc[mt][nt], ah, bl[nt]);
                    mma16816(acc[mt][nt], al, bh[nt]);
                }
            }
        }
        stage ^= 1;
    }

    const int r  = lane >> 2;
    const int c2 = (lane & 3) * 2;
#pragma unroll
    for (int mt = 0; mt < 2; mt++) {
#pragma unroll
        for (int half = 0; half < 2; half++) {
            int row = rowBase + wm * 32 + mt * 16 + half * 8 + r;
            if (row >= n) continue;
#pragma unroll
            for (int nt = 0; nt < 8; nt++) {
                int col = wn * 64 + nt * 8 + c2;
                float2 o;
                o.x = fmaxf(acc[mt][nt][half * 2 + 0], 0.f);
                o.y = fmaxf(acc[mt][nt][half * 2 + 1], 0.f);
                *(float2*)&OUT[(size_t)row * D128 + col] = o;
                if (tail != nullptr && row >= numTail)
                    *(float2*)&tail[(size_t)row * D128 + col] = o;
            }
        }
    }
}

// ---------------------------------------------------------------------------
// final fused GEMM: f = leakyrelu([F2|P0|P1] @ Wcat, 0.2)
//                   out = f / max(||f||, 1e-12) ;  K = 384
// ---------------------------------------------------------------------------
__global__ __launch_bounds__(256, 1)
void gemm_final_mma(const float* __restrict__ F2, const float* __restrict__ P0,
                    const float* __restrict__ P1, const uint32_t* __restrict__ Bt,
                    float* __restrict__ OUT, int num) {
    extern __shared__ uint32_t sm[];
    uint32_t* as_hi = sm + SM_ASHI;
    uint32_t* as_lo = sm + SM_ASLO;
    uint32_t* bs_hi = sm + SM_BSHI;
    uint32_t* bs_lo = sm + SM_BSLO;
    __shared__ float ssbuf[2][128];

    const int K = 384;
    const int KW = K * 64;
    const int tid  = threadIdx.x;
    const int lane = tid & 31;
    const int wid  = tid >> 5;
    const int wm   = wid & 3;
    const int wn   = wid >> 2;
    const int rowBase = blockIdx.x * 128;

    const int arow = tid >> 1;
    const int ahalf = tid & 1;
    const int grow = rowBase + arow;
    const bool rv  = grow < num;
    const size_t ro = (size_t)(rv ? grow : 0) * D128;

    float acc[2][8][4];
#pragma unroll
    for (int mt = 0; mt < 2; mt++)
#pragma unroll
        for (int nt = 0; nt < 8; nt++)
#pragma unroll
            for (int q = 0; q < 4; q++) acc[mt][nt][q] = 0.f;

    float4 pa, pb;
    uint4  pbh, pbl;
    {
        pa = rv ? *(const float4*)&F2[ro + ahalf * 8]     : make_float4(0, 0, 0, 0);
        pb = rv ? *(const float4*)&F2[ro + ahalf * 8 + 4] : make_float4(0, 0, 0, 0);
        pbh = *(const uint4*)&Bt[tid * 4];
        pbl = *(const uint4*)&Bt[KW + tid * 4];
    }

    int stage = 0;
    const int NK = K / 16;
#pragma unroll 1
    for (int ks = 0; ks < NK; ks++) {
        {
            uint32_t h0, l0, h1, l1, h2, l2, h3, l3;
            split2(pa.x, pa.y, h0, l0);
            split2(pa.z, pa.w, h1, l1);
            split2(pb.x, pb.y, h2, l2);
            split2(pb.z, pb.w, h3, l3);
            int aw = stage * AS_WORDS + arow * AS_STRIDE + ahalf * 4;
            *(uint4*)&as_hi[aw] = make_uint4(h0, h1, h2, h3);
            *(uint4*)&as_lo[aw] = make_uint4(l0, l1, l2, l3);
            int bw = stage * BS_WORDS + tid * 4;
            *(uint4*)&bs_hi[bw] = pbh;
            *(uint4*)&bs_lo[bw] = pbl;
        }
        __syncthreads();
        if (ks + 1 < NK) {
            int kb = (ks + 1) * 16;
            if (rv) {
                const float* s = (kb < 128) ? (F2 + ro + kb)
                               : (kb < 256) ? (P0 + ro + kb - 128)
                                            : (P1 + ro + kb - 256);
                pa = *(const float4*)&s[ahalf * 8];
                pb = *(const float4*)&s[ahalf * 8 + 4];
            }
            pbh = *(const uint4*)&Bt[(ks + 1) * BS_WORDS + tid * 4];
            pbl = *(const uint4*)&Bt[KW + (ks + 1) * BS_WORDS + tid * 4];
        }
        {
            const int r = lane >> 2;
            const int p = lane & 3;
            uint32_t bh[8][2], bl[8][2];
#pragma unroll
            for (int nt = 0; nt < 8; nt++) {
                int nn = wn * 64 + nt * 8 + r;
                uint2 th = *(const uint2*)&bs_hi[stage * BS_WORDS + (nn * 4 + p) * 2];
                uint2 tl = *(const uint2*)&bs_lo[stage * BS_WORDS + (nn * 4 + p) * 2];
                bh[nt][0] = th.x; bh[nt][1] = th.y;
                bl[nt][0] = tl.x; bl[nt][1] = tl.y;
            }
#pragma unroll
            for (int mt = 0; mt < 2; mt++) {
                int r0 = wm * 32 + mt * 16;
                int ab = stage * AS_WORDS + (r0 + r) * AS_STRIDE + p;
                uint32_t ah[4], al[4];
                ah[0] = as_hi[ab];
                ah[1] = as_hi[ab + 8 * AS_STRIDE];
                ah[2] = as_hi[ab + 4];
                ah[3] = as_hi[ab + 8 * AS_STRIDE + 4];
                al[0] = as_lo[ab];
                al[1] = as_lo[ab + 8 * AS_STRIDE];
                al[2] = as_lo[ab + 4];
                al[3] = as_lo[ab + 8 * AS_STRIDE + 4];
#pragma unroll
                for (int nt = 0; nt < 8; nt++) {
                    mma16816(acc[mt][nt], ah, bh[nt]);
                    mma16816(acc[mt][nt], ah, bl[nt]);
                    mma16816(acc[mt][nt], al, bh[nt]);
                }
            }
        }
        stage ^= 1;
    }

    const int r = lane >> 2;
    float ss[2][2] = {{0.f, 0.f}, {0.f, 0.f}};
#pragma unroll
    for (int mt = 0; mt < 2; mt++)
#pragma unroll
        for (int nt = 0; nt < 8; nt++)
#pragma unroll
            for (int q = 0; q < 4; q++) {
                float v = acc[mt][nt][q];
                v = (v > 0.f) ? v : 0.2f * v;
                acc[mt][nt][q] = v;
                ss[mt][q >> 1] = fmaf(v, v, ss[mt][q >> 1]);
            }
#pragma unroll
    for (int m = 1; m < 4; m <<= 1) {
#pragma unroll
        for (int mt = 0; mt < 2; mt++) {
            ss[mt][0] += __shfl_xor_sync(0xffffffffu, ss[mt][0], m);
            ss[mt][1] += __shfl_xor_sync(0xffffffffu, ss[mt][1], m);
        }
    }
    if ((lane & 3) == 0) {
#pragma unroll
        for (int mt = 0; mt < 2; mt++)
#pragma unroll
            for (int half = 0; half < 2; half++)
                ssbuf[wn][wm * 32 + mt * 16 + half * 8 + r] = ss[mt][half];
    }
    __syncthreads();

    const int c2 = (lane & 3) * 2;
#pragma unroll
    for (int mt = 0; mt < 2; mt++) {
#pragma unroll
        for (int half = 0; half < 2; half++) {
            int rl  = wm * 32 + mt * 16 + half * 8 + r;
            int row = rowBase + rl;
            if (row >= num) continue;
            float tot = ssbuf[0][rl] + ssbuf[1][rl];
            float inv = 1.0f / fmaxf(sqrtf(tot), 1e-12f);
#pragma unroll
            for (int nt = 0; nt < 8; nt++) {
                int col = wn * 64 + nt * 8 + c2;
                float2 o;
                o.x = acc[mt][nt][half * 2 + 0] * inv;
                o.y = acc[mt][nt][half * 2 + 1] * inv;
                *(float2*)&OUT[(size_t)row * D128 + col] = o;
            }
        }
    }
}

// ---------------------------------------------------------------------------
// launch
// ---------------------------------------------------------------------------
extern "C" void kernel_launch(void* const* d_in, const int* in_sizes, int n_in,
                              void* d_out, int out_size) {
    const float* x    = (const float*)d_in[0];
    const float* past = (const float*)d_in[1];
    const float* W1   = (const float*)d_in[2];
    const float* W2   = (const float*)d_in[3];
    const float* W0   = (const float*)d_in[4];
    const float* Wp   = (const float*)d_in[5];
    const float* WT   = (const float*)d_in[6];
    const void*  ei   = d_in[7];
    float*       out  = (float*)d_out;

    const int n   = in_sizes[0] / D128;
    const int num = in_sizes[1] / (2 * D128);
    const int E   = in_sizes[7] / 2;

    const float* p0 = past;
    const float* p1 = past + (size_t)num * D128;

    float *agg, *feat1, *feat2, *Wcat;
    int *cnt, *off, *cursor, *adj, *bsum;
    uint16_t *B1, *B2, *Bf;
    cudaGetSymbolAddress((void**)&agg,    g_agg);
    cudaGetSymbolAddress((void**)&feat1,  g_feat1);
    cudaGetSymbolAddress((void**)&feat2,  g_feat2);
    cudaGetSymbolAddress((void**)&cnt,    g_cnt);
    cudaGetSymbolAddress((void**)&off,    g_off);
    cudaGetSymbolAddress((void**)&cursor, g_cursor);
    cudaGetSymbolAddress((void**)&adj,    g_adj);
    cudaGetSymbolAddress((void**)&bsum,   g_blocksum);
    cudaGetSymbolAddress((void**)&Wcat,   g_Wcat);
    cudaGetSymbolAddress((void**)&B1,     g_B1);
    cudaGetSymbolAddress((void**)&B2,     g_B2);
    cudaGetSymbolAddress((void**)&Bf,     g_Bf);

    cudaFuncSetAttribute(gemm_sage_mma,  cudaFuncAttributeMaxDynamicSharedMemorySize, SM_TOTAL_BYTES);
    cudaFuncSetAttribute(gemm_final_mma, cudaFuncAttributeMaxDynamicSharedMemorySize, SM_TOTAL_BYTES);

    // CSR build (launch order also positions gather at the ncu capture slot)
    zdetect_kernel<<<(n + 255) / 256, 256>>>((const int*)ei, cnt, E, n);
    deg_kernel<<<(E + 255) / 256, 256>>>(ei, cnt, E);
    const int scanBlocks = (n + SCAN_CHUNK - 1) / SCAN_CHUNK;
    scan_p1<<<scanBlocks, 1024>>>(cnt, bsum, n);
    scan_p3<<<scanBlocks, 1024>>>(cnt, bsum, off, cursor, n, scanBlocks);
    scatter_kernel<<<(E + 255) / 256, 256>>>(ei, cursor, adj, E);

    const int gatherBlocks = (n + 7) / 8;
    const int gemmBlocks   = (n + 127) / 128;

    // layer 1 aggregation first (profiled slot), then weight bakes
    gather_kernel<<<gatherBlocks, 256>>>(x, adj, off, cnt, agg, n);
    {
        dim3 g(128, 3);
        wcombine_kernel<<<g, 128>>>(W0, Wp, WT, Wcat);
    }
    wprep_kernel<<<(128 * 256 + 255) / 256, 256>>>(W1, B1, 256);
    wprep_kernel<<<(128 * 256 + 255) / 256, 256>>>(W2, B2, 256);
    wprep_kernel<<<(128 * 384 + 255) / 256, 256>>>(Wcat, Bf, 384);

    // layer 1 GEMM
    gemm_sage_mma<<<gemmBlocks, 256, SM_TOTAL_BYTES>>>(x, agg, (const uint32_t*)B1,
                                                       feat1, nullptr, n, n);
    // layer 2 (tail rows >= num stream into d_out)
    gather_kernel<<<gatherBlocks, 256>>>(feat1, adj, off, cnt, agg, n);
    gemm_sage_mma<<<gemmBlocks, 256, SM_TOTAL_BYTES>>>(feat1, agg, (const uint32_t*)B2,
                                                       feat2, out, n, num);
    // fused final
    gemm_final_mma<<<(num + 127) / 128, 256, SM_TOTAL_BYTES>>>(feat2, p0, p1,
                                                               (const uint32_t*)Bf, out, num);
}

// round 8
// speedup vs baseline: 2.7124x; 1.1384x over previous
#include <cuda_runtime.h>
#include <cuda_bf16.h>
#include <cstddef>
#include <cstdint>

// ---------------------------------------------------------------------------
// dygraphSAGE on GB300 (base sm_103 target): CSR-gather aggregation +
// mma.sync bf16 hi/lo GEMMs (fragment-baked B, conflict-free smem, 2 CTA/SM)
// ---------------------------------------------------------------------------

#define D128 128
#define MAXN 131072
#define MAXE 2097152
#define SCAN_CHUNK 1024
#define MAXBLKS (MAXN / SCAN_CHUNK)   // 128

// scratch (device globals -- allocation-free per harness rules)
__device__ float g_agg  [(size_t)MAXN * D128];
__device__ float g_feat1[(size_t)MAXN * D128];
__device__ float g_feat2[(size_t)MAXN * D128];
__device__ int   g_cnt[MAXN];
__device__ int   g_off[MAXN];
__device__ int   g_cursor[MAXN];
__device__ int   g_adj[MAXE];
__device__ int   g_blocksum[MAXBLKS];
__device__ float g_Wcat[384 * D128];
__device__ int   g_is64;
// fragment-order baked weights: per plane (hi, lo): word idx
// ((ks*128 + nn)*4 + tig)*2 + w   (uint32 words, 2 bf16 each)
__device__ __align__(16) uint16_t g_B1[2 * 128 * 256];
__device__ __align__(16) uint16_t g_B2[2 * 128 * 256];
__device__ __align__(16) uint16_t g_Bf[2 * 128 * 384];

// ---------------------------------------------------------------------------
// helpers
// ---------------------------------------------------------------------------
__device__ __forceinline__ void split2(float x0, float x1, uint32_t& hi, uint32_t& lo) {
    asm("cvt.rn.bf16x2.f32 %0, %1, %2;" : "=r"(hi) : "f"(x1), "f"(x0));
    float h0 = __uint_as_float(hi << 16);
    float h1 = __uint_as_float(hi & 0xffff0000u);
    asm("cvt.rn.bf16x2.f32 %0, %1, %2;" : "=r"(lo) : "f"(x1 - h1), "f"(x0 - h0));
}

__device__ __forceinline__ void mma16816(float* c, const uint32_t* a, const uint32_t* b) {
    asm volatile("mma.sync.aligned.m16n8k16.row.col.f32.bf16.bf16.f32 "
                 "{%0,%1,%2,%3}, {%4,%5,%6,%7}, {%8,%9}, {%0,%1,%2,%3};"
                 : "+f"(c[0]), "+f"(c[1]), "+f"(c[2]), "+f"(c[3])
                 : "r"(a[0]), "r"(a[1]), "r"(a[2]), "r"(a[3]),
                   "r"(b[0]), "r"(b[1]));
}

// ---------------------------------------------------------------------------
// zero cnt + detect index dtype (block 0 samples)
// ---------------------------------------------------------------------------
__global__ void zdetect_kernel(const int* __restrict__ ei, int* __restrict__ cnt,
                               int E, int n) {
    int i = blockIdx.x * blockDim.x + threadIdx.x;
    if (i < n) cnt[i] = 0;
    if (blockIdx.x == 0) {
        __shared__ int any;
        if (threadIdx.x == 0) any = 0;
        __syncthreads();
        int c = E < 4096 ? E : 4096;
        for (int j = threadIdx.x; j < c; j += blockDim.x)
            if (ei[2 * j + 1] != 0) any = 1;
        __syncthreads();
        if (threadIdx.x == 0) g_is64 = any ? 0 : 1;
    }
}

__device__ __forceinline__ int load_idx(const void* ei, size_t pos) {
    return g_is64 ? (int)((const long long*)ei)[pos] : ((const int*)ei)[pos];
}

__global__ void deg_kernel(const void* __restrict__ ei, int* __restrict__ cnt, int E) {
    int e = blockIdx.x * blockDim.x + threadIdx.x;
    if (e < E) atomicAdd(&cnt[load_idx(ei, (size_t)E + e)], 1);
}

// ---------------------------------------------------------------------------
// 2-phase parallel exclusive scan of cnt -> off (+ cursor copy)
// ---------------------------------------------------------------------------
__global__ void scan_p1(const int* __restrict__ cnt, int* __restrict__ blocksum, int n) {
    __shared__ int red[1024];
    int b = blockIdx.x, t = threadIdx.x;
    int i = b * SCAN_CHUNK + t;
    red[t] = (i < n) ? cnt[i] : 0;
    __syncthreads();
    for (int d = 512; d > 0; d >>= 1) {
        if (t < d) red[t] += red[t + d];
        __syncthreads();
    }
    if (t == 0) blocksum[b] = red[0];
}

__global__ void scan_p3(const int* __restrict__ cnt, const int* __restrict__ blocksum,
                        int* __restrict__ off, int* __restrict__ cursor, int n, int B) {
    __shared__ int s[1024];
    __shared__ int bs[MAXBLKS];
    int b = blockIdx.x, t = threadIdx.x;
    if (t < MAXBLKS) bs[t] = (t < B) ? blocksum[t] : 0;
    __syncthreads();
    for (int d = 1; d < MAXBLKS; d <<= 1) {
        int v = 0;
        if (t < MAXBLKS && t >= d) v = bs[t - d];
        __syncthreads();
        if (t < MAXBLKS) bs[t] += v;
        __syncthreads();
    }
    int base = (b == 0) ? 0 : bs[b - 1];
    int i = b * SCAN_CHUNK + t;
    int v = (i < n) ? cnt[i] : 0;
    s[t] = v;
    __syncthreads();
    for (int d = 1; d < 1024; d <<= 1) {
        int u = (t >= d) ? s[t - d] : 0;
        __syncthreads();
        s[t] += u;
        __syncthreads();
    }
    if (i < n) {
        int e = base + s[t] - v;
        off[i] = e;
        cursor[i] = e;
    }
}

__global__ void scatter_kernel(const void* __restrict__ ei,
                               int* __restrict__ cursor, int* __restrict__ adj, int E) {
    int e = blockIdx.x * blockDim.x + threadIdx.x;
    if (e >= E) return;
    int d = load_idx(ei, (size_t)E + e);
    int s = load_idx(ei, e);
    int pos = atomicAdd(&cursor[d], 1);
    adj[pos] = s;
}

// ---------------------------------------------------------------------------
// CSR gather mean-aggregation: one warp per node, lane owns 4 features.
// Writes agg already scaled by 1/max(deg,1).
// ---------------------------------------------------------------------------
__global__ __launch_bounds__(256)
void gather_kernel(const float* __restrict__ feat, const int* __restrict__ adj,
                   const int* __restrict__ off, const int* __restrict__ cnt,
                   float* __restrict__ agg, int n) {
    int w    = (int)((blockIdx.x * (size_t)blockDim.x + threadIdx.x) >> 5);
    int lane = threadIdx.x & 31;
    if (w >= n) return;
    const int start = off[w];
    const int deg   = cnt[w];
    float ax = 0.f, ay = 0.f, az = 0.f, aw = 0.f;
    int i = 0;
    for (; i + 4 <= deg; i += 4) {
        int s0 = adj[start + i + 0];
        int s1 = adj[start + i + 1];
        int s2 = adj[start + i + 2];
        int s3 = adj[start + i + 3];
        float4 v0 = *(const float4*)&feat[(size_t)s0 * D128 + lane * 4];
        float4 v1 = *(const float4*)&feat[(size_t)s1 * D128 + lane * 4];
        float4 v2 = *(const float4*)&feat[(size_t)s2 * D128 + lane * 4];
        float4 v3 = *(const float4*)&feat[(size_t)s3 * D128 + lane * 4];
        ax += (v0.x + v1.x) + (v2.x + v3.x);
        ay += (v0.y + v1.y) + (v2.y + v3.y);
        az += (v0.z + v1.z) + (v2.z + v3.z);
        aw += (v0.w + v1.w) + (v2.w + v3.w);
    }
    for (; i < deg; i++) {
        int s = adj[start + i];
        float4 v = *(const float4*)&feat[(size_t)s * D128 + lane * 4];
        ax += v.x; ay += v.y; az += v.z; aw += v.w;
    }
    float sc = 1.0f / (float)(deg > 1 ? deg : 1);
    float4 o = make_float4(ax * sc, ay * sc, az * sc, aw * sc);
    *(float4*)&agg[(size_t)w * D128 + lane * 4] = o;
}

// ---------------------------------------------------------------------------
// temporal weight fold (Wcat [384,128] fp32)
// ---------------------------------------------------------------------------
__global__ void wcombine_kernel(const float* __restrict__ W0,
                                const float* __restrict__ Wp,
                                const float* __restrict__ WT,
                                float* __restrict__ Wcat) {
    int row = blockIdx.x;
    int m   = blockIdx.y;
    int col = threadIdx.x;
    __shared__ float L[128];
    const float* Lsrc = (m == 0) ? W0 : (Wp + (size_t)(m - 1) * 128 * 128);
    L[col] = Lsrc[row * 128 + col];
    __syncthreads();
    float s = 0.f;
#pragma unroll 8
    for (int k = 0; k < 128; k++)
        s = fmaf(L[k], WT[(size_t)(128 + k) * 128 + col], s);
    s *= (1.0f / 3.0f);
    if (m == 0) s += WT[(size_t)row * 128 + col];
    Wcat[(size_t)(m * 128 + row) * 128 + col] = s;
}

// ---------------------------------------------------------------------------
// bake W [K,128] fp32 -> fragment-order bf16 planes (hi at 0, lo at 128*K u16)
// ---------------------------------------------------------------------------
__global__ void wprep_kernel(const float* __restrict__ W, uint16_t* __restrict__ img, int K) {
    int idx = blockIdx.x * blockDim.x + threadIdx.x;
    if (idx >= 128 * K) return;
    int nn = idx / K, k = idx % K;
    float x = W[(size_t)k * 128 + nn];
    __nv_bfloat16 h = __float2bfloat16_rn(x);
    float hf = __bfloat162float(h);
    __nv_bfloat16 l = __float2bfloat16_rn(x - hf);
    int ks = k >> 4, kin = k & 15;
    int tig = (kin >> 1) & 3, w = kin >> 3, half = kin & 1;
    size_t u16pos = (size_t)((((ks * 128 + nn) * 4 + tig) * 2 + w) * 2 + half);
    img[u16pos]                     = *(uint16_t*)&h;
    img[(size_t)128 * K + u16pos]   = *(uint16_t*)&l;
}

// ---------------------------------------------------------------------------
// GEMM smem layout constants (dynamic smem, 56KB/CTA, 2 CTA/SM)
// ---------------------------------------------------------------------------
#define AS_STRIDE 20
#define AS_WORDS  (128 * AS_STRIDE)      // 2560
#define BS_WORDS  1024
#define SM_ASHI   0
#define SM_ASLO   (2 * AS_WORDS)
#define SM_BSHI   (4 * AS_WORDS)
#define SM_BSLO   (4 * AS_WORDS + 2 * BS_WORDS)
#define SM_TOTAL_BYTES ((4 * AS_WORDS + 4 * BS_WORDS) * 4)   // 57344

// ---------------------------------------------------------------------------
// SAGE layer GEMM: OUT = relu([H | AGG] @ W), K=256, AGG pre-scaled
// ---------------------------------------------------------------------------
__global__ __launch_bounds__(256, 2)
void gemm_sage_mma(const float* __restrict__ H, const float* __restrict__ AGG,
                   const uint32_t* __restrict__ Bt,
                   float* __restrict__ OUT, float* __restrict__ tail,
                   int n, int numTail) {
    extern __shared__ uint32_t sm[];
    uint32_t* as_hi = sm + SM_ASHI;
    uint32_t* as_lo = sm + SM_ASLO;
    uint32_t* bs_hi = sm + SM_BSHI;
    uint32_t* bs_lo = sm + SM_BSLO;

    const int K = 256;
    const int KW = K * 64;               // words per B plane
    const int tid  = threadIdx.x;
    const int lane = tid & 31;
    const int wid  = tid >> 5;
    const int wm   = wid & 3;
    const int wn   = wid >> 2;
    const int rowBase = blockIdx.x * 128;

    const int arow = tid >> 1;
    const int ahalf = tid & 1;           // k offset = ahalf*8 elements
    const int grow = rowBase + arow;
    const bool rv  = grow < n;
    const float* hptr = H   + (size_t)(rv ? grow : 0) * D128;
    const float* aptr = AGG + (size_t)(rv ? grow : 0) * D128;

    float acc[2][8][4];
#pragma unroll
    for (int mt = 0; mt < 2; mt++)
#pragma unroll
        for (int nt = 0; nt < 8; nt++)
#pragma unroll
            for (int q = 0; q < 4; q++) acc[mt][nt][q] = 0.f;

    float4 pa, pb;
    uint4  pbh, pbl;
    {
        pa = rv ? *(const float4*)&hptr[ahalf * 8]     : make_float4(0, 0, 0, 0);
        pb = rv ? *(const float4*)&hptr[ahalf * 8 + 4] : make_float4(0, 0, 0, 0);
        pbh = *(const uint4*)&Bt[tid * 4];
        pbl = *(const uint4*)&Bt[KW + tid * 4];
    }

    int stage = 0;
    const int NK = K / 16;
#pragma unroll 1
    for (int ks = 0; ks < NK; ks++) {
        {
            uint32_t h0, l0, h1, l1, h2, l2, h3, l3;
            split2(pa.x, pa.y, h0, l0);
            split2(pa.z, pa.w, h1, l1);
            split2(pb.x, pb.y, h2, l2);
            split2(pb.z, pb.w, h3, l3);
            int aw = stage * AS_WORDS + arow * AS_STRIDE + ahalf * 4;
            *(uint4*)&as_hi[aw] = make_uint4(h0, h1, h2, h3);
            *(uint4*)&as_lo[aw] = make_uint4(l0, l1, l2, l3);
            int bw = stage * BS_WORDS + tid * 4;
            *(uint4*)&bs_hi[bw] = pbh;
            *(uint4*)&bs_lo[bw] = pbl;
        }
        __syncthreads();
        if (ks + 1 < NK) {
            int kb = (ks + 1) * 16;
            if (rv) {
                const float* s = (kb < 128) ? (hptr + kb) : (aptr + kb - 128);
                pa = *(const float4*)&s[ahalf * 8];
                pb = *(const float4*)&s[ahalf * 8 + 4];
            }
            pbh = *(const uint4*)&Bt[(ks + 1) * BS_WORDS + tid * 4];
            pbl = *(const uint4*)&Bt[KW + (ks + 1) * BS_WORDS + tid * 4];
        }
        {
            const int r = lane >> 2;
            const int p = lane & 3;
            // hoist A fragments (both mt), conflict-free LDS
            uint32_t ah[2][4], al[2][4];
#pragma unroll
            for (int mt = 0; mt < 2; mt++) {
                int ab = stage * AS_WORDS + (wm * 32 + mt * 16 + r) * AS_STRIDE + p;
                ah[mt][0] = as_hi[ab];
                ah[mt][1] = as_hi[ab + 8 * AS_STRIDE];
                ah[mt][2] = as_hi[ab + 4];
                ah[mt][3] = as_hi[ab + 8 * AS_STRIDE + 4];
                al[mt][0] = as_lo[ab];
                al[mt][1] = as_lo[ab + 8 * AS_STRIDE];
                al[mt][2] = as_lo[ab + 4];
                al[mt][3] = as_lo[ab + 8 * AS_STRIDE + 4];
            }
            // B loaded just-in-time per nt (4 live regs)
#pragma unroll
            for (int nt = 0; nt < 8; nt++) {
                int nn = wn * 64 + nt * 8 + r;
                uint2 th = *(const uint2*)&bs_hi[stage * BS_WORDS + (nn * 4 + p) * 2];
                uint2 tl = *(const uint2*)&bs_lo[stage * BS_WORDS + (nn * 4 + p) * 2];
                uint32_t bh2[2] = {th.x, th.y};
                uint32_t bl2[2] = {tl.x, tl.y};
#pragma unroll
                for (int mt = 0; mt < 2; mt++) {
                    mma16816(acc[mt][nt], ah[mt], bh2);
                    mma16816(acc[mt][nt], ah[mt], bl2);
                    mma16816(acc[mt][nt], al[mt], bh2);
                }
            }
        }
        stage ^= 1;
    }

    const int r  = lane >> 2;
    const int c2 = (lane & 3) * 2;
#pragma unroll
    for (int mt = 0; mt < 2; mt++) {
#pragma unroll
        for (int half = 0; half < 2; half++) {
            int row = rowBase + wm * 32 + mt * 16 + half * 8 + r;
            if (row >= n) continue;
#pragma unroll
            for (int nt = 0; nt < 8; nt++) {
                int col = wn * 64 + nt * 8 + c2;
                float2 o;
                o.x = fmaxf(acc[mt][nt][half * 2 + 0], 0.f);
                o.y = fmaxf(acc[mt][nt][half * 2 + 1], 0.f);
                *(float2*)&OUT[(size_t)row * D128 + col] = o;
                if (tail != nullptr && row >= numTail)
                    *(float2*)&tail[(size_t)row * D128 + col] = o;
            }
        }
    }
}

// ---------------------------------------------------------------------------
// final fused GEMM: f = leakyrelu([F2|P0|P1] @ Wcat, 0.2)
//                   out = f / max(||f||, 1e-12) ;  K = 384
// ---------------------------------------------------------------------------
__global__ __launch_bounds__(256, 2)
void gemm_final_mma(const float* __restrict__ F2, const float* __restrict__ P0,
                    const float* __restrict__ P1, const uint32_t* __restrict__ Bt,
                    float* __restrict__ OUT, int num) {
    extern __shared__ uint32_t sm[];
    uint32_t* as_hi = sm + SM_ASHI;
    uint32_t* as_lo = sm + SM_ASLO;
    uint32_t* bs_hi = sm + SM_BSHI;
    uint32_t* bs_lo = sm + SM_BSLO;
    __shared__ float ssbuf[2][128];

    const int K = 384;
    const int KW = K * 64;
    const int tid  = threadIdx.x;
    const int lane = tid & 31;
    const int wid  = tid >> 5;
    const int wm   = wid & 3;
    const int wn   = wid >> 2;
    const int rowBase = blockIdx.x * 128;

    const int arow = tid >> 1;
    const int ahalf = tid & 1;
    const int grow = rowBase + arow;
    const bool rv  = grow < num;
    const size_t ro = (size_t)(rv ? grow : 0) * D128;

    float acc[2][8][4];
#pragma unroll
    for (int mt = 0; mt < 2; mt++)
#pragma unroll
        for (int nt = 0; nt < 8; nt++)
#pragma unroll
            for (int q = 0; q < 4; q++) acc[mt][nt][q] = 0.f;

    float4 pa, pb;
    uint4  pbh, pbl;
    {
        pa = rv ? *(const float4*)&F2[ro + ahalf * 8]     : make_float4(0, 0, 0, 0);
        pb = rv ? *(const float4*)&F2[ro + ahalf * 8 + 4] : make_float4(0, 0, 0, 0);
        pbh = *(const uint4*)&Bt[tid * 4];
        pbl = *(const uint4*)&Bt[KW + tid * 4];
    }

    int stage = 0;
    const int NK = K / 16;
#pragma unroll 1
    for (int ks = 0; ks < NK; ks++) {
        {
            uint32_t h0, l0, h1, l1, h2, l2, h3, l3;
            split2(pa.x, pa.y, h0, l0);
            split2(pa.z, pa.w, h1, l1);
            split2(pb.x, pb.y, h2, l2);
            split2(pb.z, pb.w, h3, l3);
            int aw = stage * AS_WORDS + arow * AS_STRIDE + ahalf * 4;
            *(uint4*)&as_hi[aw] = make_uint4(h0, h1, h2, h3);
            *(uint4*)&as_lo[aw] = make_uint4(l0, l1, l2, l3);
            int bw = stage * BS_WORDS + tid * 4;
            *(uint4*)&bs_hi[bw] = pbh;
            *(uint4*)&bs_lo[bw] = pbl;
        }
        __syncthreads();
        if (ks + 1 < NK) {
            int kb = (ks + 1) * 16;
            if (rv) {
                const float* s = (kb < 128) ? (F2 + ro + kb)
                               : (kb < 256) ? (P0 + ro + kb - 128)
                                            : (P1 + ro + kb - 256);
                pa = *(const float4*)&s[ahalf * 8];
                pb = *(const float4*)&s[ahalf * 8 + 4];
            }
            pbh = *(const uint4*)&Bt[(ks + 1) * BS_WORDS + tid * 4];
            pbl = *(const uint4*)&Bt[KW + (ks + 1) * BS_WORDS + tid * 4];
        }
        {
            const int r = lane >> 2;
            const int p = lane & 3;
            uint32_t ah[2][4], al[2][4];
#pragma unroll
            for (int mt = 0; mt < 2; mt++) {
                int ab = stage * AS_WORDS + (wm * 32 + mt * 16 + r) * AS_STRIDE + p;
                ah[mt][0] = as_hi[ab];
                ah[mt][1] = as_hi[ab + 8 * AS_STRIDE];
                ah[mt][2] = as_hi[ab + 4];
                ah[mt][3] = as_hi[ab + 8 * AS_STRIDE + 4];
                al[mt][0] = as_lo[ab];
                al[mt][1] = as_lo[ab + 8 * AS_STRIDE];
                al[mt][2] = as_lo[ab + 4];
                al[mt][3] = as_lo[ab + 8 * AS_STRIDE + 4];
            }
#pragma unroll
            for (int nt = 0; nt < 8; nt++) {
                int nn = wn * 64 + nt * 8 + r;
                uint2 th = *(const uint2*)&bs_hi[stage * BS_WORDS + (nn * 4 + p) * 2];
                uint2 tl = *(const uint2*)&bs_lo[stage * BS_WORDS + (nn * 4 + p) * 2];
                uint32_t bh2[2] = {th.x, th.y};
                uint32_t bl2[2] = {tl.x, tl.y};
#pragma unroll
                for (int mt = 0; mt < 2; mt++) {
                    mma16816(acc[mt][nt], ah[mt], bh2);
                    mma16816(acc[mt][nt], ah[mt], bl2);
                    mma16816(acc[mt][nt], al[mt], bh2);
                }
            }
        }
        stage ^= 1;
    }

    const int r = lane >> 2;
    float ss[2][2] = {{0.f, 0.f}, {0.f, 0.f}};
#pragma unroll
    for (int mt = 0; mt < 2; mt++)
#pragma unroll
        for (int nt = 0; nt < 8; nt++)
#pragma unroll
            for (int q = 0; q < 4; q++) {
                float v = acc[mt][nt][q];
                v = (v > 0.f) ? v : 0.2f * v;
                acc[mt][nt][q] = v;
                ss[mt][q >> 1] = fmaf(v, v, ss[mt][q >> 1]);
            }
#pragma unroll
    for (int m = 1; m < 4; m <<= 1) {
#pragma unroll
        for (int mt = 0; mt < 2; mt++) {
            ss[mt][0] += __shfl_xor_sync(0xffffffffu, ss[mt][0], m);
            ss[mt][1] += __shfl_xor_sync(0xffffffffu, ss[mt][1], m);
        }
    }
    if ((lane & 3) == 0) {
#pragma unroll
        for (int mt = 0; mt < 2; mt++)
#pragma unroll
            for (int half = 0; half < 2; half++)
                ssbuf[wn][wm * 32 + mt * 16 + half * 8 + r] = ss[mt][half];
    }
    __syncthreads();

    const int c2 = (lane & 3) * 2;
#pragma unroll
    for (int mt = 0; mt < 2; mt++) {
#pragma unroll
        for (int half = 0; half < 2; half++) {
            int rl  = wm * 32 + mt * 16 + half * 8 + r;
            int row = rowBase + rl;
            if (row >= num) continue;
            float tot = ssbuf[0][rl] + ssbuf[1][rl];
            float inv = 1.0f / fmaxf(sqrtf(tot), 1e-12f);
#pragma unroll
            for (int nt = 0; nt < 8; nt++) {
                int col = wn * 64 + nt * 8 + c2;
                float2 o;
                o.x = acc[mt][nt][half * 2 + 0] * inv;
                o.y = acc[mt][nt][half * 2 + 1] * inv;
                *(float2*)&OUT[(size_t)row * D128 + col] = o;
            }
        }
    }
}

// ---------------------------------------------------------------------------
// launch
// ---------------------------------------------------------------------------
extern "C" void kernel_launch(void* const* d_in, const int* in_sizes, int n_in,
                              void* d_out, int out_size) {
    const float* x    = (const float*)d_in[0];
    const float* past = (const float*)d_in[1];
    const float* W1   = (const float*)d_in[2];
    const float* W2   = (const float*)d_in[3];
    const float* W0   = (const float*)d_in[4];
    const float* Wp   = (const float*)d_in[5];
    const float* WT   = (const float*)d_in[6];
    const void*  ei   = d_in[7];
    float*       out  = (float*)d_out;

    const int n   = in_sizes[0] / D128;
    const int num = in_sizes[1] / (2 * D128);
    const int E   = in_sizes[7] / 2;

    const float* p0 = past;
    const float* p1 = past + (size_t)num * D128;

    float *agg, *feat1, *feat2, *Wcat;
    int *cnt, *off, *cursor, *adj, *bsum;
    uint16_t *B1, *B2, *Bf;
    cudaGetSymbolAddress((void**)&agg,    g_agg);
    cudaGetSymbolAddress((void**)&feat1,  g_feat1);
    cudaGetSymbolAddress((void**)&feat2,  g_feat2);
    cudaGetSymbolAddress((void**)&cnt,    g_cnt);
    cudaGetSymbolAddress((void**)&off,    g_off);
    cudaGetSymbolAddress((void**)&cursor, g_cursor);
    cudaGetSymbolAddress((void**)&adj,    g_adj);
    cudaGetSymbolAddress((void**)&bsum,   g_blocksum);
    cudaGetSymbolAddress((void**)&Wcat,   g_Wcat);
    cudaGetSymbolAddress((void**)&B1,     g_B1);
    cudaGetSymbolAddress((void**)&B2,     g_B2);
    cudaGetSymbolAddress((void**)&Bf,     g_Bf);

    cudaFuncSetAttribute(gemm_sage_mma,  cudaFuncAttributeMaxDynamicSharedMemorySize, SM_TOTAL_BYTES);
    cudaFuncSetAttribute(gemm_final_mma, cudaFuncAttributeMaxDynamicSharedMemorySize, SM_TOTAL_BYTES);

    // CSR build
    zdetect_kernel<<<(n + 255) / 256, 256>>>((const int*)ei, cnt, E, n);
    deg_kernel<<<(E + 255) / 256, 256>>>(ei, cnt, E);
    const int scanBlocks = (n + SCAN_CHUNK - 1) / SCAN_CHUNK;
    scan_p1<<<scanBlocks, 1024>>>(cnt, bsum, n);
    scan_p3<<<scanBlocks, 1024>>>(cnt, bsum, off, cursor, n, scanBlocks);
    scatter_kernel<<<(E + 255) / 256, 256>>>(ei, cursor, adj, E);

    const int gatherBlocks = (n + 7) / 8;
    const int gemmBlocks   = (n + 127) / 128;

    // layer 1 aggregation, then weight bakes
    gather_kernel<<<gatherBlocks, 256>>>(x, adj, off, cnt, agg, n);
    {
        dim3 g(128, 3);
        wcombine_kernel<<<g, 128>>>(W0, Wp, WT, Wcat);
    }
    wprep_kernel<<<(128 * 256 + 255) / 256, 256>>>(W1, B1, 256);
    wprep_kernel<<<(128 * 256 + 255) / 256, 256>>>(W2, B2, 256);
    wprep_kernel<<<(128 * 384 + 255) / 256, 256>>>(Wcat, Bf, 384);

    // layer 1 GEMM
    gemm_sage_mma<<<gemmBlocks, 256, SM_TOTAL_BYTES>>>(x, agg, (const uint32_t*)B1,
                                                       feat1, nullptr, n, n);
    // layer 2 (tail rows >= num stream into d_out)
    gather_kernel<<<gatherBlocks, 256>>>(feat1, adj, off, cnt, agg, n);
    gemm_sage_mma<<<gemmBlocks, 256, SM_TOTAL_BYTES>>>(feat1, agg, (const uint32_t*)B2,
                                                       feat2, out, n, num);
    // fused final
    gemm_final_mma<<<(num + 127) / 128, 256, SM_TOTAL_BYTES>>>(feat2, p0, p1,
                                                               (const uint32_t*)Bf, out, num);
}

// round 9
// speedup vs baseline: 2.7712x; 1.0217x over previous
#include <cuda_runtime.h>
#include <cuda_bf16.h>
#include <cstddef>
#include <cstdint>

// ---------------------------------------------------------------------------
// dygraphSAGE on GB300 (base sm_103 target): CSR-gather aggregation +
// mma.sync bf16 hi/lo GEMMs (fragment-baked B, conflict-free smem, 2 CTA/SM)
// + side-stream weight prep overlap
// ---------------------------------------------------------------------------

#define D128 128
#define MAXN 131072
#define MAXE 2097152
#define SCAN_CHUNK 1024
#define MAXBLKS (MAXN / SCAN_CHUNK)   // 128

// scratch (device globals -- allocation-free per harness rules)
__device__ float g_agg  [(size_t)MAXN * D128];
__device__ float g_feat1[(size_t)MAXN * D128];
__device__ float g_feat2[(size_t)MAXN * D128];
__device__ int   g_cnt[MAXN];
__device__ int   g_off[MAXN];
__device__ int   g_cursor[MAXN];
__device__ int   g_adj[MAXE];
__device__ int   g_blocksum[MAXBLKS];
__device__ float g_Wcat[384 * D128];
__device__ int   g_is64;
// fragment-order baked weights: per plane (hi, lo): word idx
// ((ks*128 + nn)*4 + tig)*2 + w   (uint32 words, 2 bf16 each)
__device__ __align__(16) uint16_t g_B1[2 * 128 * 256];
__device__ __align__(16) uint16_t g_B2[2 * 128 * 256];
__device__ __align__(16) uint16_t g_Bf[2 * 128 * 384];

// ---------------------------------------------------------------------------
// helpers
// ---------------------------------------------------------------------------
__device__ __forceinline__ void split2(float x0, float x1, uint32_t& hi, uint32_t& lo) {
    asm("cvt.rn.bf16x2.f32 %0, %1, %2;" : "=r"(hi) : "f"(x1), "f"(x0));
    float h0 = __uint_as_float(hi << 16);
    float h1 = __uint_as_float(hi & 0xffff0000u);
    asm("cvt.rn.bf16x2.f32 %0, %1, %2;" : "=r"(lo) : "f"(x1 - h1), "f"(x0 - h0));
}

__device__ __forceinline__ void mma16816(float* c, const uint32_t* a, const uint32_t* b) {
    asm volatile("mma.sync.aligned.m16n8k16.row.col.f32.bf16.bf16.f32 "
                 "{%0,%1,%2,%3}, {%4,%5,%6,%7}, {%8,%9}, {%0,%1,%2,%3};"
                 : "+f"(c[0]), "+f"(c[1]), "+f"(c[2]), "+f"(c[3])
                 : "r"(a[0]), "r"(a[1]), "r"(a[2]), "r"(a[3]),
                   "r"(b[0]), "r"(b[1]));
}

// ---------------------------------------------------------------------------
// zero cnt + detect index dtype (block 0 samples)
// ---------------------------------------------------------------------------
__global__ void zdetect_kernel(const int* __restrict__ ei, int* __restrict__ cnt,
                               int E, int n) {
    int i = blockIdx.x * blockDim.x + threadIdx.x;
    if (i < n) cnt[i] = 0;
    if (blockIdx.x == 0) {
        __shared__ int any;
        if (threadIdx.x == 0) any = 0;
        __syncthreads();
        int c = E < 4096 ? E : 4096;
        for (int j = threadIdx.x; j < c; j += blockDim.x)
            if (ei[2 * j + 1] != 0) any = 1;
        __syncthreads();
        if (threadIdx.x == 0) g_is64 = any ? 0 : 1;
    }
}

__device__ __forceinline__ int load_idx(const void* ei, size_t pos) {
    return g_is64 ? (int)((const long long*)ei)[pos] : ((const int*)ei)[pos];
}

__global__ void deg_kernel(const void* __restrict__ ei, int* __restrict__ cnt, int E) {
    int e = blockIdx.x * blockDim.x + threadIdx.x;
    if (e < E) atomicAdd(&cnt[load_idx(ei, (size_t)E + e)], 1);
}

// ---------------------------------------------------------------------------
// 2-phase parallel exclusive scan of cnt -> off (+ cursor copy)
// ---------------------------------------------------------------------------
__global__ void scan_p1(const int* __restrict__ cnt, int* __restrict__ blocksum, int n) {
    __shared__ int red[1024];
    int b = blockIdx.x, t = threadIdx.x;
    int i = b * SCAN_CHUNK + t;
    red[t] = (i < n) ? cnt[i] : 0;
    __syncthreads();
    for (int d = 512; d > 0; d >>= 1) {
        if (t < d) red[t] += red[t + d];
        __syncthreads();
    }
    if (t == 0) blocksum[b] = red[0];
}

__global__ void scan_p3(const int* __restrict__ cnt, const int* __restrict__ blocksum,
                        int* __restrict__ off, int* __restrict__ cursor, int n, int B) {
    __shared__ int s[1024];
    __shared__ int bs[MAXBLKS];
    int b = blockIdx.x, t = threadIdx.x;
    if (t < MAXBLKS) bs[t] = (t < B) ? blocksum[t] : 0;
    __syncthreads();
    for (int d = 1; d < MAXBLKS; d <<= 1) {
        int v = 0;
        if (t < MAXBLKS && t >= d) v = bs[t - d];
        __syncthreads();
        if (t < MAXBLKS) bs[t] += v;
        __syncthreads();
    }
    int base = (b == 0) ? 0 : bs[b - 1];
    int i = b * SCAN_CHUNK + t;
    int v = (i < n) ? cnt[i] : 0;
    s[t] = v;
    __syncthreads();
    for (int d = 1; d < 1024; d <<= 1) {
        int u = (t >= d) ? s[t - d] : 0;
        __syncthreads();
        s[t] += u;
        __syncthreads();
    }
    if (i < n) {
        int e = base + s[t] - v;
        off[i] = e;
        cursor[i] = e;
    }
}

__global__ void scatter_kernel(const void* __restrict__ ei,
                               int* __restrict__ cursor, int* __restrict__ adj, int E) {
    int e = blockIdx.x * blockDim.x + threadIdx.x;
    if (e >= E) return;
    int d = load_idx(ei, (size_t)E + e);
    int s = load_idx(ei, e);
    int pos = atomicAdd(&cursor[d], 1);
    adj[pos] = s;
}

// ---------------------------------------------------------------------------
// CSR gather mean-aggregation: one warp per node, lane owns 4 features.
// ---------------------------------------------------------------------------
__global__ __launch_bounds__(256)
void gather_kernel(const float* __restrict__ feat, const int* __restrict__ adj,
                   const int* __restrict__ off, const int* __restrict__ cnt,
                   float* __restrict__ agg, int n) {
    int w    = (int)((blockIdx.x * (size_t)blockDim.x + threadIdx.x) >> 5);
    int lane = threadIdx.x & 31;
    if (w >= n) return;
    const int start = off[w];
    const int deg   = cnt[w];
    float ax = 0.f, ay = 0.f, az = 0.f, aw = 0.f;
    int i = 0;
    for (; i + 4 <= deg; i += 4) {
        int s0 = adj[start + i + 0];
        int s1 = adj[start + i + 1];
        int s2 = adj[start + i + 2];
        int s3 = adj[start + i + 3];
        float4 v0 = *(const float4*)&feat[(size_t)s0 * D128 + lane * 4];
        float4 v1 = *(const float4*)&feat[(size_t)s1 * D128 + lane * 4];
        float4 v2 = *(const float4*)&feat[(size_t)s2 * D128 + lane * 4];
        float4 v3 = *(const float4*)&feat[(size_t)s3 * D128 + lane * 4];
        ax += (v0.x + v1.x) + (v2.x + v3.x);
        ay += (v0.y + v1.y) + (v2.y + v3.y);
        az += (v0.z + v1.z) + (v2.z + v3.z);
        aw += (v0.w + v1.w) + (v2.w + v3.w);
    }
    for (; i < deg; i++) {
        int s = adj[start + i];
        float4 v = *(const float4*)&feat[(size_t)s * D128 + lane * 4];
        ax += v.x; ay += v.y; az += v.z; aw += v.w;
    }
    float sc = 1.0f / (float)(deg > 1 ? deg : 1);
    float4 o = make_float4(ax * sc, ay * sc, az * sc, aw * sc);
    *(float4*)&agg[(size_t)w * D128 + lane * 4] = o;
}

// ---------------------------------------------------------------------------
// temporal weight fold (Wcat [384,128] fp32)
// ---------------------------------------------------------------------------
__global__ void wcombine_kernel(const float* __restrict__ W0,
                                const float* __restrict__ Wp,
                                const float* __restrict__ WT,
                                float* __restrict__ Wcat) {
    int row = blockIdx.x;
    int m   = blockIdx.y;
    int col = threadIdx.x;
    __shared__ float L[128];
    const float* Lsrc = (m == 0) ? W0 : (Wp + (size_t)(m - 1) * 128 * 128);
    L[col] = Lsrc[row * 128 + col];
    __syncthreads();
    float s = 0.f;
#pragma unroll 8
    for (int k = 0; k < 128; k++)
        s = fmaf(L[k], WT[(size_t)(128 + k) * 128 + col], s);
    s *= (1.0f / 3.0f);
    if (m == 0) s += WT[(size_t)row * 128 + col];
    Wcat[(size_t)(m * 128 + row) * 128 + col] = s;
}

// ---------------------------------------------------------------------------
// bake W [K,128] fp32 -> fragment-order bf16 planes (hi at 0, lo at 128*K u16)
// ---------------------------------------------------------------------------
__global__ void wprep_kernel(const float* __restrict__ W, uint16_t* __restrict__ img, int K) {
    int idx = blockIdx.x * blockDim.x + threadIdx.x;
    if (idx >= 128 * K) return;
    int nn = idx / K, k = idx % K;
    float x = W[(size_t)k * 128 + nn];
    __nv_bfloat16 h = __float2bfloat16_rn(x);
    float hf = __bfloat162float(h);
    __nv_bfloat16 l = __float2bfloat16_rn(x - hf);
    int ks = k >> 4, kin = k & 15;
    int tig = (kin >> 1) & 3, w = kin >> 3, half = kin & 1;
    size_t u16pos = (size_t)((((ks * 128 + nn) * 4 + tig) * 2 + w) * 2 + half);
    img[u16pos]                     = *(uint16_t*)&h;
    img[(size_t)128 * K + u16pos]   = *(uint16_t*)&l;
}

// ---------------------------------------------------------------------------
// GEMM smem layout constants (dynamic smem, 56KB/CTA, 2 CTA/SM)
// ---------------------------------------------------------------------------
#define AS_STRIDE 20
#define AS_WORDS  (128 * AS_STRIDE)      // 2560
#define BS_WORDS  1024
#define SM_ASHI   0
#define SM_ASLO   (2 * AS_WORDS)
#define SM_BSHI   (4 * AS_WORDS)
#define SM_BSLO   (4 * AS_WORDS + 2 * BS_WORDS)
#define SM_TOTAL_BYTES ((4 * AS_WORDS + 4 * BS_WORDS) * 4)   // 57344

// ---------------------------------------------------------------------------
// SAGE layer GEMM: OUT = relu([H | AGG] @ W), K=256, AGG pre-scaled
// rows >= numTail are written ONLY to tail (when tail != nullptr)
// ---------------------------------------------------------------------------
__global__ __launch_bounds__(256, 2)
void gemm_sage_mma(const float* __restrict__ H, const float* __restrict__ AGG,
                   const uint32_t* __restrict__ Bt,
                   float* __restrict__ OUT, float* __restrict__ tail,
                   int n, int numTail) {
    extern __shared__ uint32_t sm[];
    uint32_t* as_hi = sm + SM_ASHI;
    uint32_t* as_lo = sm + SM_ASLO;
    uint32_t* bs_hi = sm + SM_BSHI;
    uint32_t* bs_lo = sm + SM_BSLO;

    const int K = 256;
    const int KW = K * 64;               // words per B plane
    const int tid  = threadIdx.x;
    const int lane = tid & 31;
    const int wid  = tid >> 5;
    const int wm   = wid & 3;
    const int wn   = wid >> 2;
    const int rowBase = blockIdx.x * 128;

    const int arow = tid >> 1;
    const int ahalf = tid & 1;           // k offset = ahalf*8 elements
    const int grow = rowBase + arow;
    const bool rv  = grow < n;
    const float* hptr = H   + (size_t)(rv ? grow : 0) * D128;
    const float* aptr = AGG + (size_t)(rv ? grow : 0) * D128;

    float acc[2][8][4];
#pragma unroll
    for (int mt = 0; mt < 2; mt++)
#pragma unroll
        for (int nt = 0; nt < 8; nt++)
#pragma unroll
            for (int q = 0; q < 4; q++) acc[mt][nt][q] = 0.f;

    float4 pa, pb;
    uint4  pbh, pbl;
    {
        pa = rv ? *(const float4*)&hptr[ahalf * 8]     : make_float4(0, 0, 0, 0);
        pb = rv ? *(const float4*)&hptr[ahalf * 8 + 4] : make_float4(0, 0, 0, 0);
        pbh = *(const uint4*)&Bt[tid * 4];
        pbl = *(const uint4*)&Bt[KW + tid * 4];
    }

    int stage = 0;
    const int NK = K / 16;
#pragma unroll 1
    for (int ks = 0; ks < NK; ks++) {
        {
            uint32_t h0, l0, h1, l1, h2, l2, h3, l3;
            split2(pa.x, pa.y, h0, l0);
            split2(pa.z, pa.w, h1, l1);
            split2(pb.x, pb.y, h2, l2);
            split2(pb.z, pb.w, h3, l3);
            int aw = stage * AS_WORDS + arow * AS_STRIDE + ahalf * 4;
            *(uint4*)&as_hi[aw] = make_uint4(h0, h1, h2, h3);
            *(uint4*)&as_lo[aw] = make_uint4(l0, l1, l2, l3);
            int bw = stage * BS_WORDS + tid * 4;
            *(uint4*)&bs_hi[bw] = pbh;
            *(uint4*)&bs_lo[bw] = pbl;
        }
        __syncthreads();
        if (ks + 1 < NK) {
            int kb = (ks + 1) * 16;
            if (rv) {
                const float* s = (kb < 128) ? (hptr + kb) : (aptr + kb - 128);
                pa = *(const float4*)&s[ahalf * 8];
                pb = *(const float4*)&s[ahalf * 8 + 4];
            }
            pbh = *(const uint4*)&Bt[(ks + 1) * BS_WORDS + tid * 4];
            pbl = *(const uint4*)&Bt[KW + (ks + 1) * BS_WORDS + tid * 4];
        }
        {
            const int r = lane >> 2;
            const int p = lane & 3;
            uint32_t ah[2][4], al[2][4];
#pragma unroll
            for (int mt = 0; mt < 2; mt++) {
                int ab = stage * AS_WORDS + (wm * 32 + mt * 16 + r) * AS_STRIDE + p;
                ah[mt][0] = as_hi[ab];
                ah[mt][1] = as_hi[ab + 8 * AS_STRIDE];
                ah[mt][2] = as_hi[ab + 4];
                ah[mt][3] = as_hi[ab + 8 * AS_STRIDE + 4];
                al[mt][0] = as_lo[ab];
                al[mt][1] = as_lo[ab + 8 * AS_STRIDE];
                al[mt][2] = as_lo[ab + 4];
                al[mt][3] = as_lo[ab + 8 * AS_STRIDE + 4];
            }
#pragma unroll
            for (int nt = 0; nt < 8; nt++) {
                int nn = wn * 64 + nt * 8 + r;
                uint2 th = *(const uint2*)&bs_hi[stage * BS_WORDS + (nn * 4 + p) * 2];
                uint2 tl = *(const uint2*)&bs_lo[stage * BS_WORDS + (nn * 4 + p) * 2];
                uint32_t bh2[2] = {th.x, th.y};
                uint32_t bl2[2] = {tl.x, tl.y};
#pragma unroll
                for (int mt = 0; mt < 2; mt++) {
                    mma16816(acc[mt][nt], ah[mt], bh2);
                    mma16816(acc[mt][nt], ah[mt], bl2);
                    mma16816(acc[mt][nt], al[mt], bh2);
                }
            }
        }
        stage ^= 1;
    }

    const int r  = lane >> 2;
    const int c2 = (lane & 3) * 2;
#pragma unroll
    for (int mt = 0; mt < 2; mt++) {
#pragma unroll
        for (int half = 0; half < 2; half++) {
            int row = rowBase + wm * 32 + mt * 16 + half * 8 + r;
            if (row >= n) continue;
            float* dstp = (tail != nullptr && row >= numTail) ? tail : OUT;
#pragma unroll
            for (int nt = 0; nt < 8; nt++) {
                int col = wn * 64 + nt * 8 + c2;
                float2 o;
                o.x = fmaxf(acc[mt][nt][half * 2 + 0], 0.f);
                o.y = fmaxf(acc[mt][nt][half * 2 + 1], 0.f);
                *(float2*)&dstp[(size_t)row * D128 + col] = o;
            }
        }
    }
}

// ---------------------------------------------------------------------------
// final fused GEMM: f = leakyrelu([F2|P0|P1] @ Wcat, 0.2)
//                   out = f / max(||f||, 1e-12) ;  K = 384
// ---------------------------------------------------------------------------
__global__ __launch_bounds__(256, 2)
void gemm_final_mma(const float* __restrict__ F2, const float* __restrict__ P0,
                    const float* __restrict__ P1, const uint32_t* __restrict__ Bt,
                    float* __restrict__ OUT, int num) {
    extern __shared__ uint32_t sm[];
    uint32_t* as_hi = sm + SM_ASHI;
    uint32_t* as_lo = sm + SM_ASLO;
    uint32_t* bs_hi = sm + SM_BSHI;
    uint32_t* bs_lo = sm + SM_BSLO;
    __shared__ float ssbuf[2][128];

    const int K = 384;
    const int KW = K * 64;
    const int tid  = threadIdx.x;
    const int lane = tid & 31;
    const int wid  = tid >> 5;
    const int wm   = wid & 3;
    const int wn   = wid >> 2;
    const int rowBase = blockIdx.x * 128;

    const int arow = tid >> 1;
    const int ahalf = tid & 1;
    const int grow = rowBase + arow;
    const bool rv  = grow < num;
    const size_t ro = (size_t)(rv ? grow : 0) * D128;

    float acc[2][8][4];
#pragma unroll
    for (int mt = 0; mt < 2; mt++)
#pragma unroll
        for (int nt = 0; nt < 8; nt++)
#pragma unroll
            for (int q = 0; q < 4; q++) acc[mt][nt][q] = 0.f;

    float4 pa, pb;
    uint4  pbh, pbl;
    {
        pa = rv ? *(const float4*)&F2[ro + ahalf * 8]     : make_float4(0, 0, 0, 0);
        pb = rv ? *(const float4*)&F2[ro + ahalf * 8 + 4] : make_float4(0, 0, 0, 0);
        pbh = *(const uint4*)&Bt[tid * 4];
        pbl = *(const uint4*)&Bt[KW + tid * 4];
    }

    int stage = 0;
    const int NK = K / 16;
#pragma unroll 1
    for (int ks = 0; ks < NK; ks++) {
        {
            uint32_t h0, l0, h1, l1, h2, l2, h3, l3;
            split2(pa.x, pa.y, h0, l0);
            split2(pa.z, pa.w, h1, l1);
            split2(pb.x, pb.y, h2, l2);
            split2(pb.z, pb.w, h3, l3);
            int aw = stage * AS_WORDS + arow * AS_STRIDE + ahalf * 4;
            *(uint4*)&as_hi[aw] = make_uint4(h0, h1, h2, h3);
            *(uint4*)&as_lo[aw] = make_uint4(l0, l1, l2, l3);
            int bw = stage * BS_WORDS + tid * 4;
            *(uint4*)&bs_hi[bw] = pbh;
            *(uint4*)&bs_lo[bw] = pbl;
        }
        __syncthreads();
        if (ks + 1 < NK) {
            int kb = (ks + 1) * 16;
            if (rv) {
                const float* s = (kb < 128) ? (F2 + ro + kb)
                               : (kb < 256) ? (P0 + ro + kb - 128)
                                            : (P1 + ro + kb - 256);
                pa = *(const float4*)&s[ahalf * 8];
                pb = *(const float4*)&s[ahalf * 8 + 4];
            }
            pbh = *(const uint4*)&Bt[(ks + 1) * BS_WORDS + tid * 4];
            pbl = *(const uint4*)&Bt[KW + (ks + 1) * BS_WORDS + tid * 4];
        }
        {
            const int r = lane >> 2;
            const int p = lane & 3;
            uint32_t ah[2][4], al[2][4];
#pragma unroll
            for (int mt = 0; mt < 2; mt++) {
                int ab = stage * AS_WORDS + (wm * 32 + mt * 16 + r) * AS_STRIDE + p;
                ah[mt][0] = as_hi[ab];
                ah[mt][1] = as_hi[ab + 8 * AS_STRIDE];
                ah[mt][2] = as_hi[ab + 4];
                ah[mt][3] = as_hi[ab + 8 * AS_STRIDE + 4];
                al[mt][0] = as_lo[ab];
                al[mt][1] = as_lo[ab + 8 * AS_STRIDE];
                al[mt][2] = as_lo[ab + 4];
                al[mt][3] = as_lo[ab + 8 * AS_STRIDE + 4];
            }
#pragma unroll
            for (int nt = 0; nt < 8; nt++) {
                int nn = wn * 64 + nt * 8 + r;
                uint2 th = *(const uint2*)&bs_hi[stage * BS_WORDS + (nn * 4 + p) * 2];
                uint2 tl = *(const uint2*)&bs_lo[stage * BS_WORDS + (nn * 4 + p) * 2];
                uint32_t bh2[2] = {th.x, th.y};
                uint32_t bl2[2] = {tl.x, tl.y};
#pragma unroll
                for (int mt = 0; mt < 2; mt++) {
                    mma16816(acc[mt][nt], ah[mt], bh2);
                    mma16816(acc[mt][nt], ah[mt], bl2);
                    mma16816(acc[mt][nt], al[mt], bh2);
                }
            }
        }
        stage ^= 1;
    }

    const int r = lane >> 2;
    float ss[2][2] = {{0.f, 0.f}, {0.f, 0.f}};
#pragma unroll
    for (int mt = 0; mt < 2; mt++)
#pragma unroll
        for (int nt = 0; nt < 8; nt++)
#pragma unroll
            for (int q = 0; q < 4; q++) {
                float v = acc[mt][nt][q];
                v = (v > 0.f) ? v : 0.2f * v;
                acc[mt][nt][q] = v;
                ss[mt][q >> 1] = fmaf(v, v, ss[mt][q >> 1]);
            }
#pragma unroll
    for (int m = 1; m < 4; m <<= 1) {
#pragma unroll
        for (int mt = 0; mt < 2; mt++) {
            ss[mt][0] += __shfl_xor_sync(0xffffffffu, ss[mt][0], m);
            ss[mt][1] += __shfl_xor_sync(0xffffffffu, ss[mt][1], m);
        }
    }
    if ((lane & 3) == 0) {
#pragma unroll
        for (int mt = 0; mt < 2; mt++)
#pragma unroll
            for (int half = 0; half < 2; half++)
                ssbuf[wn][wm * 32 + mt * 16 + half * 8 + r] = ss[mt][half];
    }
    __syncthreads();

    const int c2 = (lane & 3) * 2;
#pragma unroll
    for (int mt = 0; mt < 2; mt++) {
#pragma unroll
        for (int half = 0; half < 2; half++) {
            int rl  = wm * 32 + mt * 16 + half * 8 + r;
            int row = rowBase + rl;
            if (row >= num) continue;
            float tot = ssbuf[0][rl] + ssbuf[1][rl];
            float inv = 1.0f / fmaxf(sqrtf(tot), 1e-12f);
#pragma unroll
            for (int nt = 0; nt < 8; nt++) {
                int col = wn * 64 + nt * 8 + c2;
                float2 o;
                o.x = acc[mt][nt][half * 2 + 0] * inv;
                o.y = acc[mt][nt][half * 2 + 1] * inv;
                *(float2*)&OUT[(size_t)row * D128 + col] = o;
            }
        }
    }
}

// ---------------------------------------------------------------------------
// launch (side stream overlaps weight prep with the CSR/gather chain)
// ---------------------------------------------------------------------------
extern "C" void kernel_launch(void* const* d_in, const int* in_sizes, int n_in,
                              void* d_out, int out_size) {
    const float* x    = (const float*)d_in[0];
    const float* past = (const float*)d_in[1];
    const float* W1   = (const float*)d_in[2];
    const float* W2   = (const float*)d_in[3];
    const float* W0   = (const float*)d_in[4];
    const float* Wp   = (const float*)d_in[5];
    const float* WT   = (const float*)d_in[6];
    const void*  ei   = d_in[7];
    float*       out  = (float*)d_out;

    const int n   = in_sizes[0] / D128;
    const int num = in_sizes[1] / (2 * D128);
    const int E   = in_sizes[7] / 2;

    const float* p0 = past;
    const float* p1 = past + (size_t)num * D128;

    float *agg, *feat1, *feat2, *Wcat;
    int *cnt, *off, *cursor, *adj, *bsum;
    uint16_t *B1, *B2, *Bf;
    cudaGetSymbolAddress((void**)&agg,    g_agg);
    cudaGetSymbolAddress((void**)&feat1,  g_feat1);
    cudaGetSymbolAddress((void**)&feat2,  g_feat2);
    cudaGetSymbolAddress((void**)&cnt,    g_cnt);
    cudaGetSymbolAddress((void**)&off,    g_off);
    cudaGetSymbolAddress((void**)&cursor, g_cursor);
    cudaGetSymbolAddress((void**)&adj,    g_adj);
    cudaGetSymbolAddress((void**)&bsum,   g_blocksum);
    cudaGetSymbolAddress((void**)&Wcat,   g_Wcat);
    cudaGetSymbolAddress((void**)&B1,     g_B1);
    cudaGetSymbolAddress((void**)&B2,     g_B2);
    cudaGetSymbolAddress((void**)&Bf,     g_Bf);

    cudaFuncSetAttribute(gemm_sage_mma,  cudaFuncAttributeMaxDynamicSharedMemorySize, SM_TOTAL_BYTES);
    cudaFuncSetAttribute(gemm_final_mma, cudaFuncAttributeMaxDynamicSharedMemorySize, SM_TOTAL_BYTES);

    // persistent side stream + events (created once; identical graph each capture)
    static cudaStream_t s_side = nullptr;
    static cudaEvent_t  s_evFork = nullptr, s_evJoin = nullptr;
    if (s_side == nullptr) {
        cudaStreamCreateWithFlags(&s_side, cudaStreamNonBlocking);
        cudaEventCreateWithFlags(&s_evFork, cudaEventDisableTiming);
        cudaEventCreateWithFlags(&s_evJoin, cudaEventDisableTiming);
    }

    // fork: weight prep on side stream (independent of CSR chain)
    cudaEventRecord(s_evFork, 0);
    cudaStreamWaitEvent(s_side, s_evFork, 0);
    {
        dim3 g(128, 3);
        wcombine_kernel<<<g, 128, 0, s_side>>>(W0, Wp, WT, Wcat);
    }
    wprep_kernel<<<(128 * 256 + 255) / 256, 256, 0, s_side>>>(W1, B1, 256);
    wprep_kernel<<<(128 * 256 + 255) / 256, 256, 0, s_side>>>(W2, B2, 256);
    wprep_kernel<<<(128 * 384 + 255) / 256, 256, 0, s_side>>>(Wcat, Bf, 384);
    cudaEventRecord(s_evJoin, s_side);

    // main stream: CSR build + layer-1 aggregation
    zdetect_kernel<<<(n + 255) / 256, 256>>>((const int*)ei, cnt, E, n);
    deg_kernel<<<(E + 255) / 256, 256>>>(ei, cnt, E);
    const int scanBlocks = (n + SCAN_CHUNK - 1) / SCAN_CHUNK;
    scan_p1<<<scanBlocks, 1024>>>(cnt, bsum, n);
    scan_p3<<<scanBlocks, 1024>>>(cnt, bsum, off, cursor, n, scanBlocks);
    scatter_kernel<<<(E + 255) / 256, 256>>>(ei, cursor, adj, E);

    const int gatherBlocks = (n + 7) / 8;
    const int gemmBlocks   = (n + 127) / 128;

    gather_kernel<<<gatherBlocks, 256>>>(x, adj, off, cnt, agg, n);

    // join: GEMMs need baked weights
    cudaStreamWaitEvent(0, s_evJoin, 0);

    // layer 1 GEMM
    gemm_sage_mma<<<gemmBlocks, 256, SM_TOTAL_BYTES>>>(x, agg, (const uint32_t*)B1,
                                                       feat1, nullptr, n, n);
    // layer 2 (tail rows >= num go straight into d_out only)
    gather_kernel<<<gatherBlocks, 256>>>(feat1, adj, off, cnt, agg, n);
    gemm_sage_mma<<<gemmBlocks, 256, SM_TOTAL_BYTES>>>(feat1, agg, (const uint32_t*)B2,
                                                       feat2, out, n, num);
    // fused final
    gemm_final_mma<<<(num + 127) / 128, 256, SM_TOTAL_BYTES>>>(feat2, p0, p1,
                                                               (const uint32_t*)Bf, out, num);
}